// round 2
// baseline (speedup 1.0000x reference)
#include <cuda_runtime.h>
#include <math.h>

// Problem constants
#define NA 32   // A
#define NB 2    // B
#define NC 16   // C

// ---------------------------------------------------------------------------
// Scratch (device globals; no allocation allowed)
// ---------------------------------------------------------------------------
__device__ float g_CG[615];                // all 15 CG matrices, flat
__device__ float g_H0[NB*NA*1*NC];         // mixed_nl per l
__device__ float g_H1[NB*NA*3*NC];
__device__ float g_H2[NB*NA*5*NC];
__device__ float g_P0[NB*NA*1*NC];         // layer output parts per l
__device__ float g_P1[NB*NA*3*NC];
__device__ float g_P2[NB*NA*5*NC];

// CG triple table (canonical id order), offsets into g_CG
__device__ const int c_trip_off[16] = {0,1,10,35,44,53,80,125,170,245,270,315,390,415,490,615};
__device__ const int c_trip_l1[15]  = {0,0,0,1,1,1,1,1,1,2,2,2,2,2,2};
__device__ const int c_trip_l2[15]  = {0,1,2,0,1,1,1,2,2,0,1,1,2,2,2};
__device__ const int c_trip_l [15]  = {0,1,2,1,0,1,2,1,2,2,1,2,0,1,2};

// Coupling entries in processing order (output l = 0 x3, 1 x6, 2 x6),
// matching _cg_product's (l1 outer, l2 inner) concat order per output l.
__device__ const int c_e_l [15] = {0,0,0, 1,1,1,1,1,1, 2,2,2,2,2,2};
__device__ const int c_e_l1[15] = {0,1,2, 0,1,1,1,2,2, 0,1,1,2,2,2};
__device__ const int c_e_l2[15] = {0,1,2, 1,0,1,2,1,2, 2,1,2,0,1,2};
__device__ const int c_e_cg[15] = {0,44,390, 1,35,53,125,270,415, 10,80,170,245,315,490};
__device__ const int c_e_tau[15]= {0,256,512, 0,256,512,768,1024,1280, 0,256,512,768,1024,1280};
// G buffer offsets per entry (sizes (2l+1)*16), + sentinel
__device__ const int c_goff[16] = {0,16,32,48,96,144,192,240,288,336,416,496,576,656,736,816};
__device__ const int c_mb[3] = {0,1,4};   // m-slot base per l

// ---------------------------------------------------------------------------
// CG coefficient init (fp64, matches the reference formula exactly)
// ---------------------------------------------------------------------------
__device__ __forceinline__ double dfact(int n){
    double r = 1.0;
    for (int k = 2; k <= n; k++) r *= (double)k;
    return r;
}

__global__ void __launch_bounds__(256) init_cg_kernel(){
    int t = blockIdx.x * blockDim.x + threadIdx.x;
    if (t >= 615) return;
    int tr = 0;
    while (c_trip_off[tr+1] <= t) tr++;
    int l1 = c_trip_l1[tr], l2 = c_trip_l2[tr], l = c_trip_l[tr];
    int loc = t - c_trip_off[tr];
    int n2 = 2*l2+1, nl = 2*l+1;
    int x = loc / (n2*nl);
    int rem = loc - x*(n2*nl);
    int y = rem / nl;
    int z = rem - y*nl;
    int m1 = x - l1, m2 = y - l2, m = z - l;
    double val = 0.0;
    if (m1 + m2 == m){
        double pre = sqrt((2.0*l+1.0)*dfact(l+l1-l2)*dfact(l-l1+l2)*dfact(l1+l2-l)/dfact(l1+l2+l+1));
        pre *= sqrt(dfact(l+m)*dfact(l-m)*dfact(l1+m1)*dfact(l1-m1)*dfact(l2+m2)*dfact(l2-m2));
        double s = 0.0;
        for (int k = 0; k <= l1+l2; k++){
            int d0=k, d1=l1+l2-l-k, d2=l1-m1-k, d3=l2+m2-k, d4=l-l2+m1+k, d5=l-l1-m2+k;
            if (d0<0||d1<0||d2<0||d3<0||d4<0||d5<0) continue;
            double term = 1.0/(dfact(d0)*dfact(d1)*dfact(d2)*dfact(d3)*dfact(d4)*dfact(d5));
            s += (k & 1) ? -term : term;
        }
        val = pre * s;
    }
    g_CG[t] = (float)val;
}

// ---------------------------------------------------------------------------
// Zero the layer-output part buffers (atomicAdd targets)
// ---------------------------------------------------------------------------
__global__ void __launch_bounds__(256) zero_parts_kernel(){
    int t = blockIdx.x * blockDim.x + threadIdx.x;
    if (t < NB*NA*1*NC) g_P0[t] = 0.f;
    if (t < NB*NA*3*NC) g_P1[t] = 0.f;
    if (t < NB*NA*5*NC) g_P2[t] = 0.f;
}

// ---------------------------------------------------------------------------
// Site kernel: per (b,i) site: mp (masked neighbor sum), CG self-product,
// mix with wnl  ->  H (g_H*)
// grid = 64 blocks (b*32+i), 256 threads
// ---------------------------------------------------------------------------
__global__ void __launch_bounds__(256) site_kernel(
    int use_inputs,
    const float* __restrict__ v0, const float* __restrict__ v1, const float* __restrict__ v2,
    const float* __restrict__ norms,
    const float* __restrict__ wnl0, const float* __restrict__ wnl1, const float* __restrict__ wnl2)
{
    int bid = blockIdx.x;
    int b = bid >> 5, i = bid & 31;
    int tid = threadIdx.x;

    __shared__ float msm[32];
    __shared__ float mpsm[9*16];
    __shared__ float Tsm[5*256];
    __shared__ float red[16*9*16];   // [r][ms][co]

    const float* P0 = use_inputs ? v0 : g_P0;
    const float* P1 = use_inputs ? v1 : g_P1;
    const float* P2 = use_inputs ? v2 : g_P2;

    if (tid < 32)
        msm[tid] = (norms[(b*NA + i)*NA + tid] < 0.5f) ? 1.f : 0.f;
    __syncthreads();

    // mp[ms][c] = sum_j conn * P[b,j,m,c]
    if (tid < 144){
        int ms = tid >> 4, c = tid & 15;
        int l, m;
        if (ms == 0){ l = 0; m = 0; } else if (ms < 4){ l = 1; m = ms-1; } else { l = 2; m = ms-4; }
        const float* P = (l==0) ? P0 : ((l==1) ? P1 : P2);
        int nm = 2*l+1;
        float s = 0.f;
        for (int j = 0; j < 32; j++)
            s += msm[j] * P[((b*NA + j)*nm + m)*NC + c];
        mpsm[tid] = s;
    }
    __syncthreads();

    float acc[9];
    #pragma unroll
    for (int k = 0; k < 9; k++) acc[k] = 0.f;
    int r = tid >> 4, co = tid & 15;
    int cT = tid >> 4, dT = tid & 15;     // for T computation

    for (int e = 0; e < 15; e++){
        int l  = c_e_l[e], l1 = c_e_l1[e], l2 = c_e_l2[e];
        int nz = 2*l+1, n1 = 2*l1+1, n2 = 2*l2+1;
        int cgo = c_e_cg[e];
        int mb1 = c_mb[l1], mb2 = c_mb[l2], mb = c_mb[l];

        // T[z, c*16+d] = sum_{x,y} CG[x,y,z] mp1[x,c] mp2[y,d]
        for (int z = 0; z < nz; z++){
            float tv = 0.f;
            for (int x = 0; x < n1; x++){
                float hx = mpsm[(mb1 + x)*16 + cT];
                for (int y = 0; y < n2; y++)
                    tv += g_CG[cgo + (x*n2 + y)*nz + z] * hx * mpsm[(mb2 + y)*16 + dT];
            }
            Tsm[z*256 + tid] = tv;
        }
        __syncthreads();

        const float* wl = (l==0) ? wnl0 : ((l==1) ? wnl1 : wnl2);
        int tau = (l==0) ? 768 : 1536;
        const float* base = wl + ((size_t)i*tau + c_e_tau[e])*NC;
        for (int it = 0; it < 16; it++){
            int row = it*16 + r;
            float w = base[row*16 + co];
            for (int z = 0; z < nz; z++)
                acc[mb + z] += Tsm[z*256 + row] * w;
        }
        __syncthreads();
    }

    // reduce over r, write H
    #pragma unroll
    for (int ms = 0; ms < 9; ms++)
        red[(r*9 + ms)*16 + co] = acc[ms];
    __syncthreads();
    if (tid < 144){
        int ms = tid >> 4, c = tid & 15;
        float s = 0.f;
        #pragma unroll
        for (int rr = 0; rr < 16; rr++) s += red[(rr*9 + ms)*16 + c];
        if (ms == 0)       g_H0[(b*NA + i)*NC + c] = s;
        else if (ms < 4)   g_H1[((b*NA + i)*3 + (ms-1))*NC + c] = s;
        else               g_H2[((b*NA + i)*5 + (ms-4))*NC + c] = s;
    }
}

// ---------------------------------------------------------------------------
// Pair kernel (DOMINANT): per (i,j) pair: Y(rel_pos), G = CG(H, Y),
// stream wrel[i,j] once (d-collapsed), accumulate, atomicAdd into g_P*
// grid = 1024 blocks (i*32+j), 256 threads
// ---------------------------------------------------------------------------
__global__ void __launch_bounds__(256) pair_kernel(
    const float* __restrict__ rel_pos,
    const float* __restrict__ wr0, const float* __restrict__ wr1, const float* __restrict__ wr2)
{
    int bid = blockIdx.x;
    int i = bid >> 5, j = bid & 31;
    int tid = threadIdx.x;

    __shared__ float Hsm[2*144];    // [b][ms][c]
    __shared__ float Ysm[2*9];      // [b][ms]
    __shared__ float Gsm[2*816];    // [b][entry blocks]
    __shared__ float red[16*288];   // [slot][(b*9+ms)*16+co]

    // load H
    for (int o = tid; o < 288; o += 256){
        int b = o / 144, rm = o - b*144;
        int ms = rm >> 4, c = rm & 15;
        float v;
        if (ms == 0)       v = g_H0[(b*NA + i)*NC + c];
        else if (ms < 4)   v = g_H1[((b*NA + i)*3 + (ms-1))*NC + c];
        else               v = g_H2[((b*NA + i)*5 + (ms-4))*NC + c];
        Hsm[o] = v;
    }
    // spherical harmonics per b
    if (tid < 2){
        int b = tid;
        const float* rp = rel_pos + ((size_t)((b*NA + i)*NA + j))*3;
        float px = rp[0], py = rp[1], pz = rp[2];
        float rr = sqrtf(px*px + py*py + pz*pz + 1e-6f);
        float x = px/rr, y = py/rr, z = pz/rr;
        Ysm[b*9+0] = 0.28209479f;
        Ysm[b*9+1] = 0.48860251f*y;
        Ysm[b*9+2] = 0.48860251f*z;
        Ysm[b*9+3] = 0.48860251f*x;
        Ysm[b*9+4] = 1.09254843f*x*y;
        Ysm[b*9+5] = 1.09254843f*y*z;
        Ysm[b*9+6] = 0.31539157f*(3.f*z*z - 1.f);
        Ysm[b*9+7] = 1.09254843f*x*z;
        Ysm[b*9+8] = 0.54627422f*(x*x - y*y);
    }
    __syncthreads();

    // G[b, e, z, c] = sum_{x,y} CG[x,y,z] * H[b, l1, x, c] * Y[b, l2, y]
    for (int o = tid; o < 1632; o += 256){
        int b = (o >= 816) ? 1 : 0;
        int rm = o - b*816;
        int e = 0;
        while (rm >= c_goff[e+1]) e++;
        int off = rm - c_goff[e];
        int l  = c_e_l[e], l1 = c_e_l1[e], l2 = c_e_l2[e];
        int nz = 2*l+1, n1 = 2*l1+1, n2 = 2*l2+1;
        int cgo = c_e_cg[e];
        int mb1 = c_mb[l1], mb2 = c_mb[l2];
        int z = off >> 4, c = off & 15;
        float s = 0.f;
        for (int x = 0; x < n1; x++){
            float hx = Hsm[b*144 + (mb1 + x)*16 + c];
            for (int y = 0; y < n2; y++)
                s += g_CG[cgo + (x*n2 + y)*nz + z] * Ysm[b*9 + mb2 + y] * hx;
        }
        Gsm[o] = s;
    }
    __syncthreads();

    // main streaming loop: thread = (cslot, co); accumulate over d and e
    float acc[18];
    #pragma unroll
    for (int t = 0; t < 18; t++) acc[t] = 0.f;
    const int cslot = tid >> 4, co = tid & 15;
    const int pair = i*NA + j;

    // l = 0 entries (e = 0..2)
    {
        const float* base0 = wr0 + (size_t)pair*768*NC;
        #pragma unroll
        for (int e = 0; e < 3; e++){
            const float* wp = base0 + e*4096 + cslot*256 + co;
            float ws = 0.f, ws2 = 0.f;
            #pragma unroll
            for (int d = 0; d < 16; d += 2){ ws += wp[d*16]; ws2 += wp[(d+1)*16]; }
            ws += ws2;
            acc[0] += Gsm[        e*16 + cslot] * ws;
            acc[9] += Gsm[816  +  e*16 + cslot] * ws;
        }
    }
    // l = 1 entries (e = 3..8)
    {
        const float* base1 = wr1 + (size_t)pair*1536*NC;
        #pragma unroll
        for (int e = 0; e < 6; e++){
            const float* wp = base1 + e*4096 + cslot*256 + co;
            float ws = 0.f, ws2 = 0.f;
            #pragma unroll
            for (int d = 0; d < 16; d += 2){ ws += wp[d*16]; ws2 += wp[(d+1)*16]; }
            ws += ws2;
            #pragma unroll
            for (int b = 0; b < 2; b++)
                #pragma unroll
                for (int z = 0; z < 3; z++)
                    acc[b*9 + 1 + z] += Gsm[b*816 + 48 + e*48 + z*16 + cslot] * ws;
        }
    }
    // l = 2 entries (e = 9..14)
    {
        const float* base2 = wr2 + (size_t)pair*1536*NC;
        #pragma unroll
        for (int e = 0; e < 6; e++){
            const float* wp = base2 + e*4096 + cslot*256 + co;
            float ws = 0.f, ws2 = 0.f;
            #pragma unroll
            for (int d = 0; d < 16; d += 2){ ws += wp[d*16]; ws2 += wp[(d+1)*16]; }
            ws += ws2;
            #pragma unroll
            for (int b = 0; b < 2; b++)
                #pragma unroll
                for (int z = 0; z < 5; z++)
                    acc[b*9 + 4 + z] += Gsm[b*816 + 336 + e*80 + z*16 + cslot] * ws;
        }
    }

    // cross-slot reduction, then atomicAdd (sum over j across blocks)
    #pragma unroll
    for (int t = 0; t < 18; t++)
        red[cslot*288 + t*16 + co] = acc[t];
    __syncthreads();
    for (int o = tid; o < 288; o += 256){
        float s = 0.f;
        #pragma unroll
        for (int sl = 0; sl < 16; sl++) s += red[sl*288 + o];
        int cc = o & 15;
        int t  = o >> 4;
        int b  = t / 9;
        int ms = t - b*9;
        if (ms == 0)
            atomicAdd(&g_P0[(b*NA + i)*NC + cc], s);
        else if (ms < 4)
            atomicAdd(&g_P1[((b*NA + i)*3 + (ms-1))*NC + cc], s);
        else
            atomicAdd(&g_P2[((b*NA + i)*5 + (ms-4))*NC + cc], s);
    }
}

// ---------------------------------------------------------------------------
// Scalars kernel: invariants from layer-output parts -> out rows for this layer
// grid = 64 blocks (b*32+a), 256 threads
// ---------------------------------------------------------------------------
__global__ void __launch_bounds__(256) scalars_kernel(float* __restrict__ out, int layer){
    int bid = blockIdx.x;
    int b = bid >> 5, a = bid & 31;
    int tid = threadIdx.x;
    __shared__ float Psm[144];
    if (tid < 144){
        int ms = tid >> 4, c = tid & 15;
        float v;
        if (ms == 0)       v = g_P0[(b*NA + a)*NC + c];
        else if (ms < 4)   v = g_P1[((b*NA + a)*3 + (ms-1))*NC + c];
        else               v = g_P2[((b*NA + a)*5 + (ms-4))*NC + c];
        Psm[tid] = v;
    }
    __syncthreads();
    float* o = out + (size_t)((layer*NB + b)*NA + a)*784;
    if (tid < 16) o[tid] = Psm[tid];
    int cc = tid >> 4, dd = tid & 15;
    o[16  + tid] = Psm[cc]*Psm[dd];
    float s1 = 0.f;
    #pragma unroll
    for (int m = 0; m < 3; m++) s1 += Psm[(1+m)*16 + cc]*Psm[(1+m)*16 + dd];
    o[272 + tid] = s1;
    float s2 = 0.f;
    #pragma unroll
    for (int m = 0; m < 5; m++) s2 += Psm[(4+m)*16 + cc]*Psm[(4+m)*16 + dd];
    o[528 + tid] = s2;
}

// ---------------------------------------------------------------------------
// Launch
// ---------------------------------------------------------------------------
extern "C" void kernel_launch(void* const* d_in, const int* in_sizes, int n_in,
                              void* d_out, int out_size)
{
    const float* v0    = (const float*)d_in[0];
    const float* v1    = (const float*)d_in[1];
    const float* v2    = (const float*)d_in[2];
    const float* rel   = (const float*)d_in[3];
    const float* norms = (const float*)d_in[4];
    const float* wnl[2][3]  = {{(const float*)d_in[5],  (const float*)d_in[7],  (const float*)d_in[9]},
                               {(const float*)d_in[11], (const float*)d_in[13], (const float*)d_in[15]}};
    const float* wrel[2][3] = {{(const float*)d_in[6],  (const float*)d_in[8],  (const float*)d_in[10]},
                               {(const float*)d_in[12], (const float*)d_in[14], (const float*)d_in[16]}};
    float* out = (float*)d_out;

    init_cg_kernel<<<3, 256>>>();
    for (int L = 0; L < 2; L++){
        site_kernel<<<64, 256>>>(L == 0 ? 1 : 0, v0, v1, v2, norms,
                                 wnl[L][0], wnl[L][1], wnl[L][2]);
        zero_parts_kernel<<<20, 256>>>();
        pair_kernel<<<1024, 256>>>(rel, wrel[L][0], wrel[L][1], wrel[L][2]);
        scalars_kernel<<<64, 256>>>(out, L);
    }
}

// round 7
// speedup vs baseline: 2.4365x; 2.4365x over previous
#include <cuda_runtime.h>
#include <math.h>

#define NA 32
#define NB 2
#define NC 16

// ---------------------------------------------------------------------------
// Compile-time tables (accessed only with template/constexpr indices)
// ---------------------------------------------------------------------------
constexpr int E_L_[15]   = {0,0,0, 1,1,1,1,1,1, 2,2,2,2,2,2};
constexpr int E_L1_[15]  = {0,1,2, 0,1,1,1,2,2, 0,1,1,2,2,2};
constexpr int E_L2_[15]  = {0,1,2, 1,0,1,2,1,2, 2,1,2,0,1,2};
constexpr int E_CG_[15]  = {0,44,390, 1,35,53,125,270,415, 10,80,170,245,315,490};
constexpr int E_TAU_[15] = {0,256,512, 0,256,512,768,1024,1280, 0,256,512,768,1024,1280};
constexpr int E_GOFF_[15]= {0,16,32, 48,96,144,192,240,288, 336,416,496,576,656,736};
constexpr int MB_[3] = {0,1,4};
__host__ __device__ constexpr int SB_(int e){ return e<3 ? e : (e<9 ? 3+(e-3)*3 : 21+(e-9)*5); }

// compile-time CG coefficients (fp64 math, matches reference formula)
constexpr double cfact(int n){ double r=1.0; for (int k=2;k<=n;k++) r*= (double)k; return r; }
constexpr double csqrt_(double x){ double g = x > 1.0 ? x : 1.0; for (int i=0;i<80;i++) g = 0.5*(g + x/g); return g; }
constexpr double cg_coeff(int l1,int l2,int l,int m1,int m2,int m){
    int lo = l1>l2 ? l1-l2 : l2-l1;
    if (m1+m2 != m || l < lo || l > l1+l2) return 0.0;
    double pre = csqrt_((2.0*l+1.0)*cfact(l+l1-l2)*cfact(l-l1+l2)*cfact(l1+l2-l)/cfact(l1+l2+l+1));
    pre *= csqrt_(cfact(l+m)*cfact(l-m)*cfact(l1+m1)*cfact(l1-m1)*cfact(l2+m2)*cfact(l2-m2));
    double s = 0.0;
    for (int k=0;k<=l1+l2;k++){
        int d0=k,d1=l1+l2-l-k,d2=l1-m1-k,d3=l2+m2-k,d4=l-l2+m1+k,d5=l-l1-m2+k;
        if (d0<0||d1<0||d2<0||d3<0||d4<0||d5<0) continue;
        double t = 1.0/(cfact(d0)*cfact(d1)*cfact(d2)*cfact(d3)*cfact(d4)*cfact(d5));
        s += (k&1) ? -t : t;
    }
    return pre*s;
}
struct CGTable {
    float v[615];
    constexpr CGTable() : v{} {
        int off = 0;
        for (int l1=0;l1<=2;l1++)
            for (int l2=0;l2<=2;l2++){
                int lmin = l1>l2 ? l1-l2 : l2-l1;
                int lmax = (l1+l2) < 2 ? (l1+l2) : 2;
                for (int l=lmin;l<=lmax;l++){
                    int n1=2*l1+1, n2=2*l2+1, nl=2*l+1;
                    for (int x=0;x<n1;x++)
                        for (int y=0;y<n2;y++)
                            for (int z=0;z<nl;z++)
                                v[off + (x*n2+y)*nl + z] = (float)cg_coeff(l1,l2,l, x-l1, y-l2, z-l);
                    off += n1*n2*nl;
                }
            }
    }
};
__constant__ CGTable CGT{};   // static (constexpr) initialization — no init kernel needed

// ---------------------------------------------------------------------------
// Scratch (device globals; no allocation allowed)
// ---------------------------------------------------------------------------
__device__ float g_H0[NB*NA*1*NC];
__device__ float g_H1[NB*NA*3*NC];
__device__ float g_H2[NB*NA*5*NC];
__device__ float g_P0[NB*NA*1*NC];
__device__ float g_P1[NB*NA*3*NC];
__device__ float g_P2[NB*NA*5*NC];

// ---------------------------------------------------------------------------
// Zero the atomic accumulation buffers
// ---------------------------------------------------------------------------
__global__ void __launch_bounds__(256) zero_parts_kernel(){
    int t = blockIdx.x * blockDim.x + threadIdx.x;
    if (t < NB*NA*1*NC) g_P0[t] = 0.f;
    if (t < NB*NA*3*NC) g_P1[t] = 0.f;
    if (t < NB*NA*5*NC) g_P2[t] = 0.f;
}

// ---------------------------------------------------------------------------
// Site kernel (fully unrolled per entry via templates)
// ---------------------------------------------------------------------------
template<int E>
__device__ __forceinline__ void site_entry(int tid, int r, int co,
    const float* __restrict__ mpsm, float* __restrict__ Tsm, float* __restrict__ acc,
    const float* __restrict__ w0b, const float* __restrict__ w1b, const float* __restrict__ w2b)
{
    constexpr int l  = E_L_[E], l1 = E_L1_[E], l2 = E_L2_[E];
    constexpr int nz = 2*l+1, n1 = 2*l1+1, n2 = 2*l2+1;
    constexpr int cgo = E_CG_[E], mb1 = MB_[l1], mb2 = MB_[l2], mb = MB_[l];

    // T[z][tid] : tid = c*16 + d  (c = r, d = co)
    #pragma unroll
    for (int z = 0; z < nz; z++){
        float tv = 0.f;
        #pragma unroll
        for (int x = 0; x < n1; x++){
            float hx = mpsm[(mb1+x)*16 + r];
            #pragma unroll
            for (int y = 0; y < n2; y++)
                tv += CGT.v[cgo + (x*n2+y)*nz + z] * hx * mpsm[(mb2+y)*16 + co];
        }
        Tsm[z*256 + tid] = tv;
    }
    __syncthreads();

    const float* base = (l==0 ? w0b : (l==1 ? w1b : w2b)) + E_TAU_[E]*16;
    #pragma unroll
    for (int it = 0; it < 16; it++){
        float w = base[(it*16 + r)*16 + co];
        #pragma unroll
        for (int z = 0; z < nz; z++)
            acc[mb+z] += Tsm[z*256 + it*16 + r] * w;
    }
    __syncthreads();
}

template<int E>
__device__ __forceinline__ void site_all(int tid, int r, int co,
    const float* __restrict__ mpsm, float* __restrict__ Tsm, float* __restrict__ acc,
    const float* __restrict__ w0b, const float* __restrict__ w1b, const float* __restrict__ w2b)
{
    site_entry<E>(tid, r, co, mpsm, Tsm, acc, w0b, w1b, w2b);
    if constexpr (E+1 < 15) site_all<E+1>(tid, r, co, mpsm, Tsm, acc, w0b, w1b, w2b);
}

__global__ void __launch_bounds__(256) site_kernel(
    int use_inputs,
    const float* __restrict__ v0, const float* __restrict__ v1, const float* __restrict__ v2,
    const float* __restrict__ norms,
    const float* __restrict__ wnl0, const float* __restrict__ wnl1, const float* __restrict__ wnl2)
{
    int bid = blockIdx.x;
    int b = bid >> 5, i = bid & 31;
    int tid = threadIdx.x;

    __shared__ __align__(16) float msm[32];
    __shared__ __align__(16) float mpsm[9*16];
    __shared__ __align__(16) float Tsm[5*256];
    __shared__ __align__(16) float red[16*9*16];

    const float* P0 = use_inputs ? v0 : g_P0;
    const float* P1 = use_inputs ? v1 : g_P1;
    const float* P2 = use_inputs ? v2 : g_P2;

    if (tid < 32)
        msm[tid] = (norms[(b*NA + i)*NA + tid] < 0.5f) ? 1.f : 0.f;
    __syncthreads();

    if (tid < 144){
        int ms = tid >> 4, c = tid & 15;
        int l, m;
        if (ms == 0){ l = 0; m = 0; } else if (ms < 4){ l = 1; m = ms-1; } else { l = 2; m = ms-4; }
        const float* P = (l==0) ? P0 : ((l==1) ? P1 : P2);
        int nm = 2*l+1;
        float s = 0.f;
        #pragma unroll 8
        for (int j = 0; j < 32; j++)
            s += msm[j] * P[((b*NA + j)*nm + m)*NC + c];
        mpsm[tid] = s;
    }
    __syncthreads();

    float acc[9];
    #pragma unroll
    for (int k = 0; k < 9; k++) acc[k] = 0.f;
    int r = tid >> 4, co = tid & 15;

    const float* w0b = wnl0 + (size_t)i*768*16;
    const float* w1b = wnl1 + (size_t)i*1536*16;
    const float* w2b = wnl2 + (size_t)i*1536*16;
    site_all<0>(tid, r, co, mpsm, Tsm, acc, w0b, w1b, w2b);

    #pragma unroll
    for (int ms = 0; ms < 9; ms++)
        red[(r*9 + ms)*16 + co] = acc[ms];
    __syncthreads();
    if (tid < 144){
        int ms = tid >> 4, c = tid & 15;
        float s = 0.f;
        #pragma unroll
        for (int rr = 0; rr < 16; rr++) s += red[(rr*9 + ms)*16 + c];
        if (ms == 0)       g_H0[(b*NA + i)*NC + c] = s;
        else if (ms < 4)   g_H1[((b*NA + i)*3 + (ms-1))*NC + c] = s;
        else               g_H2[((b*NA + i)*5 + (ms-4))*NC + c] = s;
    }
}

// ---------------------------------------------------------------------------
// Pair kernel helpers
// ---------------------------------------------------------------------------
template<int E>
__device__ __forceinline__ void g_entry(int wid, int gb, int gc,
    const float* __restrict__ Hsm, const float* __restrict__ Ysm, float* __restrict__ Gsm)
{
    constexpr int l  = E_L_[E], l1 = E_L1_[E], l2 = E_L2_[E];
    constexpr int nz = 2*l+1, n1 = 2*l1+1, n2 = 2*l2+1;
    constexpr int cgo = E_CG_[E], mb1 = MB_[l1], mb2 = MB_[l2], goff = E_GOFF_[E];
    #pragma unroll
    for (int z = 0; z < nz; z++){
        if (((SB_(E) + z) & 7) == wid){
            float s = 0.f;
            #pragma unroll
            for (int x = 0; x < n1; x++){
                float hx = Hsm[gb*144 + (mb1+x)*16 + gc];
                #pragma unroll
                for (int y = 0; y < n2; y++)
                    s += CGT.v[cgo + (x*n2+y)*nz + z] * Ysm[gb*9 + mb2 + y] * hx;
            }
            Gsm[gb*816 + goff + z*16 + gc] = s;
        }
    }
}

template<int E>
__device__ __forceinline__ void g_all(int wid, int gb, int gc,
    const float* __restrict__ Hsm, const float* __restrict__ Ysm, float* __restrict__ Gsm)
{
    g_entry<E>(wid, gb, gc, Hsm, Ysm, Gsm);
    if constexpr (E+1 < 15) g_all<E+1>(wid, gb, gc, Hsm, Ysm, Gsm);
}

template<int E>
__device__ __forceinline__ void stream_entry(
    const float* __restrict__ b0, const float* __restrict__ b1, const float* __restrict__ b2,
    float* __restrict__ Wsum, int cslot, int dq, int coq)
{
    const float* bp;
    if constexpr (E < 3)      bp = b0 + E*4096;
    else if constexpr (E < 9) bp = b1 + (E-3)*4096;
    else                      bp = b2 + (E-9)*4096;

    float4 w0 = *(const float4*)(bp);
    float4 w1 = *(const float4*)(bp + 64);
    float4 w2 = *(const float4*)(bp + 128);
    float4 w3 = *(const float4*)(bp + 192);

    float sx = (w0.x + w1.x) + (w2.x + w3.x);
    float sy = (w0.y + w1.y) + (w2.y + w3.y);
    float sz = (w0.z + w1.z) + (w2.z + w3.z);
    float sw = (w0.w + w1.w) + (w2.w + w3.w);

    sx += __shfl_xor_sync(0xffffffffu, sx, 4);
    sy += __shfl_xor_sync(0xffffffffu, sy, 4);
    sz += __shfl_xor_sync(0xffffffffu, sz, 4);
    sw += __shfl_xor_sync(0xffffffffu, sw, 4);
    sx += __shfl_xor_sync(0xffffffffu, sx, 8);
    sy += __shfl_xor_sync(0xffffffffu, sy, 8);
    sz += __shfl_xor_sync(0xffffffffu, sz, 8);
    sw += __shfl_xor_sync(0xffffffffu, sw, 8);

    if (dq == 0){
        float4 o = make_float4(sx, sy, sz, sw);
        *(float4*)&Wsum[E*256 + cslot*16 + coq*4] = o;
    }
}

template<int E>
__device__ __forceinline__ void stream_all(
    const float* __restrict__ b0, const float* __restrict__ b1, const float* __restrict__ b2,
    float* __restrict__ Wsum, int cslot, int dq, int coq)
{
    stream_entry<E>(b0, b1, b2, Wsum, cslot, dq, coq);
    if constexpr (E+1 < 15) stream_all<E+1>(b0, b1, b2, Wsum, cslot, dq, coq);
}

// ---------------------------------------------------------------------------
// Pair kernel (DOMINANT, DRAM-bound streaming)
// grid = 1024 (i*32+j), 256 threads, all blocks resident in one wave
// ---------------------------------------------------------------------------
__global__ void __launch_bounds__(256, 7) pair_kernel(
    const float* __restrict__ rel_pos,
    const float* __restrict__ wr0, const float* __restrict__ wr1, const float* __restrict__ wr2)
{
    __shared__ __align__(16) float Hsm[288];
    __shared__ __align__(16) float Ysm[20];
    __shared__ __align__(16) float Gsm[1632];
    __shared__ __align__(16) float Wsum[3840];

    const int bid = blockIdx.x;
    const int i = bid >> 5, j = bid & 31;
    const int tid = threadIdx.x;

    for (int o = tid; o < 288; o += 256){
        int b = (o >= 144); int rm = o - b*144;
        int ms = rm >> 4, c = rm & 15;
        float v;
        if (ms == 0)     v = g_H0[(b*NA + i)*NC + c];
        else if (ms < 4) v = g_H1[((b*NA + i)*3 + (ms-1))*NC + c];
        else             v = g_H2[((b*NA + i)*5 + (ms-4))*NC + c];
        Hsm[o] = v;
    }
    if (tid < 2){
        int b = tid;
        const float* rp = rel_pos + ((size_t)((b*NA + i)*NA + j))*3;
        float px = rp[0], py = rp[1], pz = rp[2];
        float rr = sqrtf(px*px + py*py + pz*pz + 1e-6f);
        float x = px/rr, y = py/rr, z = pz/rr;
        Ysm[b*9+0] = 0.28209479f;
        Ysm[b*9+1] = 0.48860251f*y;
        Ysm[b*9+2] = 0.48860251f*z;
        Ysm[b*9+3] = 0.48860251f*x;
        Ysm[b*9+4] = 1.09254843f*x*y;
        Ysm[b*9+5] = 1.09254843f*y*z;
        Ysm[b*9+6] = 0.31539157f*(3.f*z*z - 1.f);
        Ysm[b*9+7] = 1.09254843f*x*z;
        Ysm[b*9+8] = 0.54627422f*(x*x - y*y);
    }
    __syncthreads();

    // G phase: 51 (entry,z) slots distributed across the 8 warps
    {
        int wid = tid >> 5, gb = (tid >> 4) & 1, gc = tid & 15;
        g_all<0>(wid, gb, gc, Hsm, Ysm, Gsm);
    }

    // Streaming phase: LDG.128, shfl d-reduction, no barriers
    const int cslot = tid >> 4, dq = (tid >> 2) & 3, coq = tid & 3;
    const size_t pr = (size_t)(i*NA + j);
    const int lofs = cslot*256 + dq*16 + coq*4;
    const float* b0 = wr0 + pr*12288 + lofs;
    const float* b1 = wr1 + pr*24576 + lofs;
    const float* b2 = wr2 + pr*24576 + lofs;
    stream_all<0>(b0, b1, b2, Wsum, cslot, dq, coq);
    __syncthreads();

    // Final small matvec + atomic accumulation over j
    for (int o = tid; o < 288; o += 256){
        int co = o & 15;
        int t = o >> 4;
        int b = (t >= 9);
        int ms = t - b*9;
        float s = 0.f;
        if (ms == 0){
            #pragma unroll
            for (int e = 0; e < 3; e++)
                #pragma unroll
                for (int c = 0; c < 16; c++)
                    s += Gsm[b*816 + e*16 + c] * Wsum[e*256 + c*16 + co];
            atomicAdd(&g_P0[(b*NA + i)*NC + co], s);
        } else if (ms < 4){
            int z = ms - 1;
            #pragma unroll
            for (int ee = 0; ee < 6; ee++)
                #pragma unroll
                for (int c = 0; c < 16; c++)
                    s += Gsm[b*816 + 48 + ee*48 + z*16 + c] * Wsum[(3+ee)*256 + c*16 + co];
            atomicAdd(&g_P1[((b*NA + i)*3 + z)*NC + co], s);
        } else {
            int z = ms - 4;
            #pragma unroll
            for (int ee = 0; ee < 6; ee++)
                #pragma unroll
                for (int c = 0; c < 16; c++)
                    s += Gsm[b*816 + 336 + ee*80 + z*16 + c] * Wsum[(9+ee)*256 + c*16 + co];
            atomicAdd(&g_P2[((b*NA + i)*5 + z)*NC + co], s);
        }
    }
}

// ---------------------------------------------------------------------------
// Scalars kernel
// ---------------------------------------------------------------------------
__global__ void __launch_bounds__(256) scalars_kernel(float* __restrict__ out, int layer){
    int bid = blockIdx.x;
    int b = bid >> 5, a = bid & 31;
    int tid = threadIdx.x;
    __shared__ __align__(16) float Psm[144];
    if (tid < 144){
        int ms = tid >> 4, c = tid & 15;
        float v;
        if (ms == 0)       v = g_P0[(b*NA + a)*NC + c];
        else if (ms < 4)   v = g_P1[((b*NA + a)*3 + (ms-1))*NC + c];
        else               v = g_P2[((b*NA + a)*5 + (ms-4))*NC + c];
        Psm[tid] = v;
    }
    __syncthreads();
    float* o = out + (size_t)((layer*NB + b)*NA + a)*784;
    if (tid < 16) o[tid] = Psm[tid];
    int cc = tid >> 4, dd = tid & 15;
    o[16  + tid] = Psm[cc]*Psm[dd];
    float s1 = 0.f;
    #pragma unroll
    for (int m = 0; m < 3; m++) s1 += Psm[(1+m)*16 + cc]*Psm[(1+m)*16 + dd];
    o[272 + tid] = s1;
    float s2 = 0.f;
    #pragma unroll
    for (int m = 0; m < 5; m++) s2 += Psm[(4+m)*16 + cc]*Psm[(4+m)*16 + dd];
    o[528 + tid] = s2;
}

// ---------------------------------------------------------------------------
// Launch
// ---------------------------------------------------------------------------
extern "C" void kernel_launch(void* const* d_in, const int* in_sizes, int n_in,
                              void* d_out, int out_size)
{
    const float* v0    = (const float*)d_in[0];
    const float* v1    = (const float*)d_in[1];
    const float* v2    = (const float*)d_in[2];
    const float* rel   = (const float*)d_in[3];
    const float* norms = (const float*)d_in[4];
    const float* wnl[2][3]  = {{(const float*)d_in[5],  (const float*)d_in[7],  (const float*)d_in[9]},
                               {(const float*)d_in[11], (const float*)d_in[13], (const float*)d_in[15]}};
    const float* wrel[2][3] = {{(const float*)d_in[6],  (const float*)d_in[8],  (const float*)d_in[10]},
                               {(const float*)d_in[12], (const float*)d_in[14], (const float*)d_in[16]}};
    float* out = (float*)d_out;

    for (int L = 0; L < 2; L++){
        site_kernel<<<64, 256>>>(L == 0 ? 1 : 0, v0, v1, v2, norms,
                                 wnl[L][0], wnl[L][1], wnl[L][2]);
        zero_parts_kernel<<<20, 256>>>();
        pair_kernel<<<1024, 256>>>(rel, wrel[L][0], wrel[L][1], wrel[L][2]);
        scalars_kernel<<<64, 256>>>(out, L);
    }
}

// round 8
// speedup vs baseline: 3.0729x; 1.2612x over previous
#include <cuda_runtime.h>
#include <math.h>

#define NA 32
#define NB 2
#define NC 16

// ---------------------------------------------------------------------------
// Compile-time tables
// ---------------------------------------------------------------------------
constexpr int E_L_[15]   = {0,0,0, 1,1,1,1,1,1, 2,2,2,2,2,2};
constexpr int E_L1_[15]  = {0,1,2, 0,1,1,1,2,2, 0,1,1,2,2,2};
constexpr int E_L2_[15]  = {0,1,2, 1,0,1,2,1,2, 2,1,2,0,1,2};
constexpr int E_CG_[15]  = {0,44,390, 1,35,53,125,270,415, 10,80,170,245,315,490};
constexpr int E_TAU_[15] = {0,256,512, 0,256,512,768,1024,1280, 0,256,512,768,1024,1280};
constexpr int E_GOFF_[15]= {0,16,32, 48,96,144,192,240,288, 336,416,496,576,656,736};
constexpr int MB_[3] = {0,1,4};
__host__ __device__ constexpr int SB_(int e){ return e<3 ? e : (e<9 ? 3+(e-3)*3 : 21+(e-9)*5); }

constexpr double cfact(int n){ double r=1.0; for (int k=2;k<=n;k++) r*= (double)k; return r; }
constexpr double csqrt_(double x){ double g = x > 1.0 ? x : 1.0; for (int i=0;i<80;i++) g = 0.5*(g + x/g); return g; }
constexpr double cg_coeff(int l1,int l2,int l,int m1,int m2,int m){
    int lo = l1>l2 ? l1-l2 : l2-l1;
    if (m1+m2 != m || l < lo || l > l1+l2) return 0.0;
    double pre = csqrt_((2.0*l+1.0)*cfact(l+l1-l2)*cfact(l-l1+l2)*cfact(l1+l2-l)/cfact(l1+l2+l+1));
    pre *= csqrt_(cfact(l+m)*cfact(l-m)*cfact(l1+m1)*cfact(l1-m1)*cfact(l2+m2)*cfact(l2-m2));
    double s = 0.0;
    for (int k=0;k<=l1+l2;k++){
        int d0=k,d1=l1+l2-l-k,d2=l1-m1-k,d3=l2+m2-k,d4=l-l2+m1+k,d5=l-l1-m2+k;
        if (d0<0||d1<0||d2<0||d3<0||d4<0||d5<0) continue;
        double t = 1.0/(cfact(d0)*cfact(d1)*cfact(d2)*cfact(d3)*cfact(d4)*cfact(d5));
        s += (k&1) ? -t : t;
    }
    return pre*s;
}
struct CGTable {
    float v[615];
    constexpr CGTable() : v{} {
        int off = 0;
        for (int l1=0;l1<=2;l1++)
            for (int l2=0;l2<=2;l2++){
                int lmin = l1>l2 ? l1-l2 : l2-l1;
                int lmax = (l1+l2) < 2 ? (l1+l2) : 2;
                for (int l=lmin;l<=lmax;l++){
                    int n1=2*l1+1, n2=2*l2+1, nl=2*l+1;
                    for (int x=0;x<n1;x++)
                        for (int y=0;y<n2;y++)
                            for (int z=0;z<nl;z++)
                                v[off + (x*n2+y)*nl + z] = (float)cg_coeff(l1,l2,l, x-l1, y-l2, z-l);
                    off += n1*n2*nl;
                }
            }
    }
};
__constant__ CGTable CGT{};

// ---------------------------------------------------------------------------
// Scratch — P double-buffered so zeroing happens once upfront
// ---------------------------------------------------------------------------
__device__ float g_H0[NB*NA*1*NC];
__device__ float g_H1[NB*NA*3*NC];
__device__ float g_H2[NB*NA*5*NC];
__device__ float g_P0[2][NB*NA*1*NC];
__device__ float g_P1[2][NB*NA*3*NC];
__device__ float g_P2[2][NB*NA*5*NC];

__global__ void __launch_bounds__(256) zero_parts_kernel(){
    int t = blockIdx.x * blockDim.x + threadIdx.x;
    if (t < 2*NB*NA*1*NC) ((float*)g_P0)[t] = 0.f;
    if (t < 2*NB*NA*3*NC) ((float*)g_P1)[t] = 0.f;
    if (t < 2*NB*NA*5*NC) ((float*)g_P2)[t] = 0.f;
}

// ---------------------------------------------------------------------------
// Site kernel: batched T (2 groups, 4 syncs total), barrier-free weight stream
// ---------------------------------------------------------------------------
template<int E, int BASE>
__device__ __forceinline__ void site_T(int tid, int r, int co,
    const float* __restrict__ mpsm, float* __restrict__ Tsm)
{
    constexpr int l  = E_L_[E], l1 = E_L1_[E], l2 = E_L2_[E];
    constexpr int nz = 2*l+1, n1 = 2*l1+1, n2 = 2*l2+1;
    constexpr int cgo = E_CG_[E], mb1 = MB_[l1], mb2 = MB_[l2];
    constexpr int sb = SB_(E) - BASE;
    #pragma unroll
    for (int z = 0; z < nz; z++){
        float tv = 0.f;
        #pragma unroll
        for (int x = 0; x < n1; x++){
            float hx = mpsm[(mb1+x)*16 + r];
            #pragma unroll
            for (int y = 0; y < n2; y++)
                tv += CGT.v[cgo + (x*n2+y)*nz + z] * hx * mpsm[(mb2+y)*16 + co];
        }
        Tsm[(sb+z)*256 + tid] = tv;
    }
}

template<int E, int BASE>
__device__ __forceinline__ void site_W(int r, int co,
    const float* __restrict__ Tsm, float* __restrict__ acc,
    const float* __restrict__ w0b, const float* __restrict__ w1b, const float* __restrict__ w2b)
{
    constexpr int l = E_L_[E];
    constexpr int nz = 2*l+1, mb = MB_[l];
    constexpr int sb = SB_(E) - BASE;
    const float* base = (l==0 ? w0b : (l==1 ? w1b : w2b)) + E_TAU_[E]*16;
    #pragma unroll
    for (int it = 0; it < 16; it++){
        float w = base[(it*16 + r)*16 + co];
        #pragma unroll
        for (int z = 0; z < nz; z++)
            acc[mb+z] += Tsm[(sb+z)*256 + it*16 + r] * w;
    }
}

template<int E, int E_END, int BASE>
__device__ __forceinline__ void site_T_all(int tid, int r, int co,
    const float* __restrict__ mpsm, float* __restrict__ Tsm)
{
    site_T<E, BASE>(tid, r, co, mpsm, Tsm);
    if constexpr (E+1 < E_END) site_T_all<E+1, E_END, BASE>(tid, r, co, mpsm, Tsm);
}

template<int E, int E_END, int BASE>
__device__ __forceinline__ void site_W_all(int r, int co,
    const float* __restrict__ Tsm, float* __restrict__ acc,
    const float* __restrict__ w0b, const float* __restrict__ w1b, const float* __restrict__ w2b)
{
    site_W<E, BASE>(r, co, Tsm, acc, w0b, w1b, w2b);
    if constexpr (E+1 < E_END) site_W_all<E+1, E_END, BASE>(r, co, Tsm, acc, w0b, w1b, w2b);
}

__global__ void __launch_bounds__(256) site_kernel(
    int use_inputs,
    const float* __restrict__ v0, const float* __restrict__ v1, const float* __restrict__ v2,
    const float* __restrict__ norms,
    const float* __restrict__ wnl0, const float* __restrict__ wnl1, const float* __restrict__ wnl2)
{
    int bid = blockIdx.x;
    int b = bid >> 5, i = bid & 31;
    int tid = threadIdx.x;

    __shared__ __align__(16) float msm[32];
    __shared__ __align__(16) float mpsm[9*16];
    __shared__ __align__(16) float Tsm[30*256];   // max(21,30) slices
    __shared__ __align__(16) float red[16*9*16];

    const float* P0 = use_inputs ? v0 : g_P0[0];
    const float* P1 = use_inputs ? v1 : g_P1[0];
    const float* P2 = use_inputs ? v2 : g_P2[0];

    if (tid < 32)
        msm[tid] = (norms[(b*NA + i)*NA + tid] < 0.5f) ? 1.f : 0.f;
    __syncthreads();

    if (tid < 144){
        int ms = tid >> 4, c = tid & 15;
        int l, m;
        if (ms == 0){ l = 0; m = 0; } else if (ms < 4){ l = 1; m = ms-1; } else { l = 2; m = ms-4; }
        const float* P = (l==0) ? P0 : ((l==1) ? P1 : P2);
        int nm = 2*l+1;
        float s = 0.f;
        #pragma unroll 8
        for (int j = 0; j < 32; j++)
            s += msm[j] * P[((b*NA + j)*nm + m)*NC + c];
        mpsm[tid] = s;
    }
    __syncthreads();

    float acc[9];
    #pragma unroll
    for (int k = 0; k < 9; k++) acc[k] = 0.f;
    int r = tid >> 4, co = tid & 15;

    const float* w0b = wnl0 + (size_t)i*768*16;
    const float* w1b = wnl1 + (size_t)i*1536*16;
    const float* w2b = wnl2 + (size_t)i*1536*16;

    // group A: entries 0..8 (21 slices)
    site_T_all<0, 9, 0>(tid, r, co, mpsm, Tsm);
    __syncthreads();
    site_W_all<0, 9, 0>(r, co, Tsm, acc, w0b, w1b, w2b);
    __syncthreads();
    // group B: entries 9..14 (30 slices)
    site_T_all<9, 15, 21>(tid, r, co, mpsm, Tsm);
    __syncthreads();
    site_W_all<9, 15, 21>(r, co, Tsm, acc, w0b, w1b, w2b);

    #pragma unroll
    for (int ms = 0; ms < 9; ms++)
        red[(r*9 + ms)*16 + co] = acc[ms];
    __syncthreads();
    if (tid < 144){
        int ms = tid >> 4, c = tid & 15;
        float s = 0.f;
        #pragma unroll
        for (int rr = 0; rr < 16; rr++) s += red[(rr*9 + ms)*16 + c];
        if (ms == 0)       g_H0[(b*NA + i)*NC + c] = s;
        else if (ms < 4)   g_H1[((b*NA + i)*3 + (ms-1))*NC + c] = s;
        else               g_H2[((b*NA + i)*5 + (ms-4))*NC + c] = s;
    }
}

// ---------------------------------------------------------------------------
// Pair kernel: G helpers
// ---------------------------------------------------------------------------
template<int E>
__device__ __forceinline__ void g_entry(int wid, int gb, int gc,
    const float* __restrict__ Hsm, const float* __restrict__ Ysm, float* __restrict__ Gsm)
{
    constexpr int l  = E_L_[E], l1 = E_L1_[E], l2 = E_L2_[E];
    constexpr int nz = 2*l+1, n1 = 2*l1+1, n2 = 2*l2+1;
    constexpr int cgo = E_CG_[E], mb1 = MB_[l1], mb2 = MB_[l2], goff = E_GOFF_[E];
    #pragma unroll
    for (int z = 0; z < nz; z++){
        if (((SB_(E) + z) & 7) == wid){
            float s = 0.f;
            #pragma unroll
            for (int x = 0; x < n1; x++){
                float hx = Hsm[gb*144 + (mb1+x)*16 + gc];
                #pragma unroll
                for (int y = 0; y < n2; y++)
                    s += CGT.v[cgo + (x*n2+y)*nz + z] * Ysm[gb*9 + mb2 + y] * hx;
            }
            Gsm[gb*816 + goff + z*16 + gc] = s;
        }
    }
}

template<int E>
__device__ __forceinline__ void g_all(int wid, int gb, int gc,
    const float* __restrict__ Hsm, const float* __restrict__ Ysm, float* __restrict__ Gsm)
{
    g_entry<E>(wid, gb, gc, Hsm, Ysm, Gsm);
    if constexpr (E+1 < 15) g_all<E+1>(wid, gb, gc, Hsm, Ysm, Gsm);
}

// ---------------------------------------------------------------------------
// Pair kernel: per-thread d-chunk streaming (no shfl, no barriers, MLP=16)
// grid = 1024 (i*32+j), 256 threads, 7 blocks/SM -> one resident wave
// ---------------------------------------------------------------------------
__global__ void __launch_bounds__(256, 7) pair_kernel(
    const float* __restrict__ rel_pos,
    const float* __restrict__ wr0, const float* __restrict__ wr1, const float* __restrict__ wr2,
    int buf)
{
    __shared__ __align__(16) float Hsm[288];
    __shared__ __align__(16) float Ysm[20];
    __shared__ __align__(16) float Gsm[1632];
    __shared__ __align__(16) float Wsum[3840];

    const int bid = blockIdx.x;
    const int i = bid >> 5, j = bid & 31;
    const int tid = threadIdx.x;

    for (int o = tid; o < 288; o += 256){
        int b = (o >= 144); int rm = o - b*144;
        int ms = rm >> 4, c = rm & 15;
        float v;
        if (ms == 0)     v = g_H0[(b*NA + i)*NC + c];
        else if (ms < 4) v = g_H1[((b*NA + i)*3 + (ms-1))*NC + c];
        else             v = g_H2[((b*NA + i)*5 + (ms-4))*NC + c];
        Hsm[o] = v;
    }
    if (tid < 2){
        int b = tid;
        const float* rp = rel_pos + ((size_t)((b*NA + i)*NA + j))*3;
        float px = rp[0], py = rp[1], pz = rp[2];
        float rr = sqrtf(px*px + py*py + pz*pz + 1e-6f);
        float x = px/rr, y = py/rr, z = pz/rr;
        Ysm[b*9+0] = 0.28209479f;
        Ysm[b*9+1] = 0.48860251f*y;
        Ysm[b*9+2] = 0.48860251f*z;
        Ysm[b*9+3] = 0.48860251f*x;
        Ysm[b*9+4] = 1.09254843f*x*y;
        Ysm[b*9+5] = 1.09254843f*y*z;
        Ysm[b*9+6] = 0.31539157f*(3.f*z*z - 1.f);
        Ysm[b*9+7] = 1.09254843f*x*z;
        Ysm[b*9+8] = 0.54627422f*(x*x - y*y);
    }
    __syncthreads();

    // Streaming phase: thread = (group g, c, co-quad) owns whole d-chunks.
    // 16 independent stride-64B float4 loads per entry, no shuffles/barriers.
    {
        const int g = tid >> 6, sub = tid & 63;
        const int c = sub >> 2, coq = sub & 3;
        const size_t pr = (size_t)(i*NA + j);
        const int lofs = c*256 + coq*4;
        #pragma unroll
        for (int k = 0; k < 4; k++){
            const int e = g + k*4;
            if (e < 15){
                const float* bp;
                if (e < 3)      bp = wr0 + pr*12288 + (size_t)e*4096;
                else if (e < 9) bp = wr1 + pr*24576 + (size_t)(e-3)*4096;
                else            bp = wr2 + pr*24576 + (size_t)(e-9)*4096;
                bp += lofs;
                float4 a0 = make_float4(0.f,0.f,0.f,0.f);
                float4 a1 = make_float4(0.f,0.f,0.f,0.f);
                #pragma unroll
                for (int d = 0; d < 16; d += 2){
                    float4 w0 = *(const float4*)(bp + d*16);
                    float4 w1 = *(const float4*)(bp + (d+1)*16);
                    a0.x += w0.x; a0.y += w0.y; a0.z += w0.z; a0.w += w0.w;
                    a1.x += w1.x; a1.y += w1.y; a1.z += w1.z; a1.w += w1.w;
                }
                a0.x += a1.x; a0.y += a1.y; a0.z += a1.z; a0.w += a1.w;
                *(float4*)&Wsum[e*256 + c*16 + coq*4] = a0;
            }
        }
    }

    // G phase (tiny ALU, overlaps the in-flight stream loads)
    {
        int wid = tid >> 5, gb = (tid >> 4) & 1, gc = tid & 15;
        g_all<0>(wid, gb, gc, Hsm, Ysm, Gsm);
    }
    __syncthreads();

    // Final small matvec + atomic accumulation over j
    float* P0 = g_P0[buf];
    float* P1 = g_P1[buf];
    float* P2 = g_P2[buf];
    for (int o = tid; o < 288; o += 256){
        int co = o & 15;
        int t = o >> 4;
        int b = (t >= 9);
        int ms = t - b*9;
        float s = 0.f;
        if (ms == 0){
            #pragma unroll
            for (int e = 0; e < 3; e++)
                #pragma unroll
                for (int c = 0; c < 16; c++)
                    s += Gsm[b*816 + e*16 + c] * Wsum[e*256 + c*16 + co];
            atomicAdd(&P0[(b*NA + i)*NC + co], s);
        } else if (ms < 4){
            int z = ms - 1;
            #pragma unroll
            for (int ee = 0; ee < 6; ee++)
                #pragma unroll
                for (int c = 0; c < 16; c++)
                    s += Gsm[b*816 + 48 + ee*48 + z*16 + c] * Wsum[(3+ee)*256 + c*16 + co];
            atomicAdd(&P1[((b*NA + i)*3 + z)*NC + co], s);
        } else {
            int z = ms - 4;
            #pragma unroll
            for (int ee = 0; ee < 6; ee++)
                #pragma unroll
                for (int c = 0; c < 16; c++)
                    s += Gsm[b*816 + 336 + ee*80 + z*16 + c] * Wsum[(9+ee)*256 + c*16 + co];
            atomicAdd(&P2[((b*NA + i)*5 + z)*NC + co], s);
        }
    }
}

// ---------------------------------------------------------------------------
// Scalars kernel
// ---------------------------------------------------------------------------
__global__ void __launch_bounds__(256) scalars_kernel(float* __restrict__ out, int layer){
    int bid = blockIdx.x;
    int b = bid >> 5, a = bid & 31;
    int tid = threadIdx.x;
    __shared__ __align__(16) float Psm[144];
    if (tid < 144){
        int ms = tid >> 4, c = tid & 15;
        float v;
        if (ms == 0)       v = g_P0[layer][(b*NA + a)*NC + c];
        else if (ms < 4)   v = g_P1[layer][((b*NA + a)*3 + (ms-1))*NC + c];
        else               v = g_P2[layer][((b*NA + a)*5 + (ms-4))*NC + c];
        Psm[tid] = v;
    }
    __syncthreads();
    float* o = out + (size_t)((layer*NB + b)*NA + a)*784;
    if (tid < 16) o[tid] = Psm[tid];
    int cc = tid >> 4, dd = tid & 15;
    o[16  + tid] = Psm[cc]*Psm[dd];
    float s1 = 0.f;
    #pragma unroll
    for (int m = 0; m < 3; m++) s1 += Psm[(1+m)*16 + cc]*Psm[(1+m)*16 + dd];
    o[272 + tid] = s1;
    float s2 = 0.f;
    #pragma unroll
    for (int m = 0; m < 5; m++) s2 += Psm[(4+m)*16 + cc]*Psm[(4+m)*16 + dd];
    o[528 + tid] = s2;
}

// ---------------------------------------------------------------------------
// Launch: 7 kernels (zero once upfront; P double-buffered)
// ---------------------------------------------------------------------------
extern "C" void kernel_launch(void* const* d_in, const int* in_sizes, int n_in,
                              void* d_out, int out_size)
{
    const float* v0    = (const float*)d_in[0];
    const float* v1    = (const float*)d_in[1];
    const float* v2    = (const float*)d_in[2];
    const float* rel   = (const float*)d_in[3];
    const float* norms = (const float*)d_in[4];
    const float* wnl[2][3]  = {{(const float*)d_in[5],  (const float*)d_in[7],  (const float*)d_in[9]},
                               {(const float*)d_in[11], (const float*)d_in[13], (const float*)d_in[15]}};
    const float* wrel[2][3] = {{(const float*)d_in[6],  (const float*)d_in[8],  (const float*)d_in[10]},
                               {(const float*)d_in[12], (const float*)d_in[14], (const float*)d_in[16]}};
    float* out = (float*)d_out;

    zero_parts_kernel<<<72, 256>>>();
    for (int L = 0; L < 2; L++){
        site_kernel<<<64, 256>>>(L == 0 ? 1 : 0, v0, v1, v2, norms,
                                 wnl[L][0], wnl[L][1], wnl[L][2]);
        pair_kernel<<<1024, 256>>>(rel, wrel[L][0], wrel[L][1], wrel[L][2], L);
        scalars_kernel<<<64, 256>>>(out, L);
    }
}

// round 9
// speedup vs baseline: 3.3608x; 1.0937x over previous
#include <cuda_runtime.h>
#include <math.h>

#define NA 32
#define NB 2
#define NC 16

// ---------------------------------------------------------------------------
// Compile-time tables
// ---------------------------------------------------------------------------
constexpr int E_L_[15]   = {0,0,0, 1,1,1,1,1,1, 2,2,2,2,2,2};
constexpr int E_L1_[15]  = {0,1,2, 0,1,1,1,2,2, 0,1,1,2,2,2};
constexpr int E_L2_[15]  = {0,1,2, 1,0,1,2,1,2, 2,1,2,0,1,2};
constexpr int E_CG_[15]  = {0,44,390, 1,35,53,125,270,415, 10,80,170,245,315,490};
constexpr int E_TAU_[15] = {0,256,512, 0,256,512,768,1024,1280, 0,256,512,768,1024,1280};
constexpr int E_GOFF_[15]= {0,16,32, 48,96,144,192,240,288, 336,416,496,576,656,736};
constexpr int MB_[3] = {0,1,4};
__host__ __device__ constexpr int SB_(int e){ return e<3 ? e : (e<9 ? 3+(e-3)*3 : 21+(e-9)*5); }

constexpr double cfact(int n){ double r=1.0; for (int k=2;k<=n;k++) r*= (double)k; return r; }
constexpr double csqrt_(double x){ double g = x > 1.0 ? x : 1.0; for (int i=0;i<80;i++) g = 0.5*(g + x/g); return g; }
constexpr double cg_coeff(int l1,int l2,int l,int m1,int m2,int m){
    int lo = l1>l2 ? l1-l2 : l2-l1;
    if (m1+m2 != m || l < lo || l > l1+l2) return 0.0;
    double pre = csqrt_((2.0*l+1.0)*cfact(l+l1-l2)*cfact(l-l1+l2)*cfact(l1+l2-l)/cfact(l1+l2+l+1));
    pre *= csqrt_(cfact(l+m)*cfact(l-m)*cfact(l1+m1)*cfact(l1-m1)*cfact(l2+m2)*cfact(l2-m2));
    double s = 0.0;
    for (int k=0;k<=l1+l2;k++){
        int d0=k,d1=l1+l2-l-k,d2=l1-m1-k,d3=l2+m2-k,d4=l-l2+m1+k,d5=l-l1-m2+k;
        if (d0<0||d1<0||d2<0||d3<0||d4<0||d5<0) continue;
        double t = 1.0/(cfact(d0)*cfact(d1)*cfact(d2)*cfact(d3)*cfact(d4)*cfact(d5));
        s += (k&1) ? -t : t;
    }
    return pre*s;
}
struct CGTable {
    float v[615];
    constexpr CGTable() : v{} {
        int off = 0;
        for (int l1=0;l1<=2;l1++)
            for (int l2=0;l2<=2;l2++){
                int lmin = l1>l2 ? l1-l2 : l2-l1;
                int lmax = (l1+l2) < 2 ? (l1+l2) : 2;
                for (int l=lmin;l<=lmax;l++){
                    int n1=2*l1+1, n2=2*l2+1, nl=2*l+1;
                    for (int x=0;x<n1;x++)
                        for (int y=0;y<n2;y++)
                            for (int z=0;z<nl;z++)
                                v[off + (x*n2+y)*nl + z] = (float)cg_coeff(l1,l2,l, x-l1, y-l2, z-l);
                    off += n1*n2*nl;
                }
            }
    }
};
__constant__ CGTable CGT{};

// ---------------------------------------------------------------------------
// Scratch
// ---------------------------------------------------------------------------
__device__ float g_H0[NB*NA*1*NC];
__device__ float g_H1[NB*NA*3*NC];
__device__ float g_H2[NB*NA*5*NC];
__device__ float g_P0[2][NB*NA*1*NC];
__device__ float g_P1[2][NB*NA*3*NC];
__device__ float g_P2[2][NB*NA*5*NC];

__global__ void __launch_bounds__(256) zero_parts_kernel(){
    int t = blockIdx.x * blockDim.x + threadIdx.x;
    if (t < 2*NB*NA*1*NC) ((float*)g_P0)[t] = 0.f;
    if (t < 2*NB*NA*3*NC) ((float*)g_P1)[t] = 0.f;
    if (t < 2*NB*NA*5*NC) ((float*)g_P2)[t] = 0.f;
}

// ---------------------------------------------------------------------------
// Site kernel: grid (64 sites, 3 l-groups). Group g exclusively owns g_H{g}.
// ---------------------------------------------------------------------------
template<int E, int BASE>
__device__ __forceinline__ void site_T(int tid, int r, int co,
    const float* __restrict__ mpsm, float* __restrict__ Tsm)
{
    constexpr int l  = E_L_[E], l1 = E_L1_[E], l2 = E_L2_[E];
    constexpr int nz = 2*l+1, n1 = 2*l1+1, n2 = 2*l2+1;
    constexpr int cgo = E_CG_[E], mb1 = MB_[l1], mb2 = MB_[l2];
    constexpr int sb = SB_(E) - BASE;
    #pragma unroll
    for (int z = 0; z < nz; z++){
        float tv = 0.f;
        #pragma unroll
        for (int x = 0; x < n1; x++){
            float hx = mpsm[(mb1+x)*16 + r];
            #pragma unroll
            for (int y = 0; y < n2; y++)
                tv += CGT.v[cgo + (x*n2+y)*nz + z] * hx * mpsm[(mb2+y)*16 + co];
        }
        Tsm[(sb+z)*256 + tid] = tv;
    }
}

template<int E, int BASE>
__device__ __forceinline__ void site_W(int r, int co,
    const float* __restrict__ Tsm, float* __restrict__ acc,
    const float* __restrict__ wb)
{
    constexpr int l = E_L_[E];
    constexpr int nz = 2*l+1;
    constexpr int sb = SB_(E) - BASE;
    const float* base = wb + E_TAU_[E]*16;
    #pragma unroll
    for (int it = 0; it < 16; it++){
        float w = __ldcs(base + (it*16 + r)*16 + co);
        #pragma unroll
        for (int z = 0; z < nz; z++)
            acc[z] += Tsm[(sb+z)*256 + it*16 + r] * w;
    }
}

template<int E, int E_END, int BASE>
__device__ __forceinline__ void site_T_all(int tid, int r, int co,
    const float* __restrict__ mpsm, float* __restrict__ Tsm)
{
    site_T<E, BASE>(tid, r, co, mpsm, Tsm);
    if constexpr (E+1 < E_END) site_T_all<E+1, E_END, BASE>(tid, r, co, mpsm, Tsm);
}

template<int E, int E_END, int BASE>
__device__ __forceinline__ void site_W_all(int r, int co,
    const float* __restrict__ Tsm, float* __restrict__ acc,
    const float* __restrict__ wb)
{
    site_W<E, BASE>(r, co, Tsm, acc, wb);
    if constexpr (E+1 < E_END) site_W_all<E+1, E_END, BASE>(r, co, Tsm, acc, wb);
}

// Per-group driver: T slices, barrier, weight stream, reduce, direct H write.
template<int L>
__device__ __forceinline__ void site_group(int b, int i, int tid, int r, int co,
    const float* __restrict__ mpsm, float* __restrict__ Tsm, float* __restrict__ red,
    const float* __restrict__ wb)
{
    constexpr int nz = 2*L+1;
    constexpr int E0 = (L==0) ? 0 : (L==1 ? 3 : 9);
    constexpr int E1 = (L==0) ? 3 : (L==1 ? 9 : 15);
    constexpr int BASE = SB_(E0);

    float acc[nz];
    #pragma unroll
    for (int z = 0; z < nz; z++) acc[z] = 0.f;

    site_T_all<E0, E1, BASE>(tid, r, co, mpsm, Tsm);
    __syncthreads();
    site_W_all<E0, E1, BASE>(r, co, Tsm, acc, wb);

    #pragma unroll
    for (int z = 0; z < nz; z++)
        red[(r*nz + z)*16 + co] = acc[z];
    __syncthreads();
    if (tid < nz*16){
        int z = tid >> 4, c = tid & 15;
        float s = 0.f;
        #pragma unroll
        for (int rr = 0; rr < 16; rr++) s += red[(rr*nz + z)*16 + c];
        if constexpr (L == 0) g_H0[(b*NA + i)*NC + c] = s;
        else if constexpr (L == 1) g_H1[((b*NA + i)*3 + z)*NC + c] = s;
        else g_H2[((b*NA + i)*5 + z)*NC + c] = s;
    }
}

__global__ void __launch_bounds__(256) site_kernel(
    int use_inputs,
    const float* __restrict__ v0, const float* __restrict__ v1, const float* __restrict__ v2,
    const float* __restrict__ norms,
    const float* __restrict__ wnl0, const float* __restrict__ wnl1, const float* __restrict__ wnl2,
    int doScal, float* __restrict__ out)
{
    int bi = blockIdx.x;
    int g  = blockIdx.y;
    int b = bi >> 5, i = bi & 31;
    int tid = threadIdx.x;

    __shared__ __align__(16) float msm[32];
    __shared__ __align__(16) float mpsm[9*16];
    __shared__ __align__(16) float Tsm[30*256];
    __shared__ __align__(16) float red[16*5*16];
    __shared__ __align__(16) float Psm[144];

    const float* P0 = use_inputs ? v0 : g_P0[0];
    const float* P1 = use_inputs ? v1 : g_P1[0];
    const float* P2 = use_inputs ? v2 : g_P2[0];

    if (tid < 32)
        msm[tid] = (norms[(b*NA + i)*NA + tid] < 0.5f) ? 1.f : 0.f;
    __syncthreads();

    if (tid < 144){
        int ms = tid >> 4, c = tid & 15;
        int l, m;
        if (ms == 0){ l = 0; m = 0; } else if (ms < 4){ l = 1; m = ms-1; } else { l = 2; m = ms-4; }
        const float* P = (l==0) ? P0 : ((l==1) ? P1 : P2);
        int nm = 2*l+1;
        float s = 0.f;
        #pragma unroll 8
        for (int j = 0; j < 32; j++)
            s += msm[j] * P[((b*NA + j)*nm + m)*NC + c];
        mpsm[tid] = s;
    }
    __syncthreads();

    int r = tid >> 4, co = tid & 15;
    if (g == 0)
        site_group<0>(b, i, tid, r, co, mpsm, Tsm, red, wnl0 + (size_t)i*768*16);
    else if (g == 1)
        site_group<1>(b, i, tid, r, co, mpsm, Tsm, red, wnl1 + (size_t)i*1536*16);
    else
        site_group<2>(b, i, tid, r, co, mpsm, Tsm, red, wnl2 + (size_t)i*1536*16);

    // Fused scalars for the PREVIOUS layer (P[0] is final by the time this runs)
    if (doScal && g == 0){
        __syncthreads();
        if (tid < 144){
            int ms = tid >> 4, c = tid & 15;
            float v;
            if (ms == 0)       v = g_P0[0][(b*NA + i)*NC + c];
            else if (ms < 4)   v = g_P1[0][((b*NA + i)*3 + (ms-1))*NC + c];
            else               v = g_P2[0][((b*NA + i)*5 + (ms-4))*NC + c];
            Psm[tid] = v;
        }
        __syncthreads();
        float* o = out + (size_t)((0*NB + b)*NA + i)*784;
        if (tid < 16) o[tid] = Psm[tid];
        int cc = tid >> 4, dd = tid & 15;
        o[16  + tid] = Psm[cc]*Psm[dd];
        float s1 = 0.f;
        #pragma unroll
        for (int m = 0; m < 3; m++) s1 += Psm[(1+m)*16 + cc]*Psm[(1+m)*16 + dd];
        o[272 + tid] = s1;
        float s2 = 0.f;
        #pragma unroll
        for (int m = 0; m < 5; m++) s2 += Psm[(4+m)*16 + cc]*Psm[(4+m)*16 + dd];
        o[528 + tid] = s2;
    }
}

// ---------------------------------------------------------------------------
// Pair kernel: G helpers
// ---------------------------------------------------------------------------
template<int E>
__device__ __forceinline__ void g_entry(int wid, int gb, int gc,
    const float* __restrict__ Hsm, const float* __restrict__ Ysm, float* __restrict__ Gsm)
{
    constexpr int l  = E_L_[E], l1 = E_L1_[E], l2 = E_L2_[E];
    constexpr int nz = 2*l+1, n1 = 2*l1+1, n2 = 2*l2+1;
    constexpr int cgo = E_CG_[E], mb1 = MB_[l1], mb2 = MB_[l2], goff = E_GOFF_[E];
    #pragma unroll
    for (int z = 0; z < nz; z++){
        if (((SB_(E) + z) & 7) == wid){
            float s = 0.f;
            #pragma unroll
            for (int x = 0; x < n1; x++){
                float hx = Hsm[gb*144 + (mb1+x)*16 + gc];
                #pragma unroll
                for (int y = 0; y < n2; y++)
                    s += CGT.v[cgo + (x*n2+y)*nz + z] * Ysm[gb*9 + mb2 + y] * hx;
            }
            Gsm[gb*816 + goff + z*16 + gc] = s;
        }
    }
}

template<int E>
__device__ __forceinline__ void g_all(int wid, int gb, int gc,
    const float* __restrict__ Hsm, const float* __restrict__ Ysm, float* __restrict__ Gsm)
{
    g_entry<E>(wid, gb, gc, Hsm, Ysm, Gsm);
    if constexpr (E+1 < 15) g_all<E+1>(wid, gb, gc, Hsm, Ysm, Gsm);
}

// ---------------------------------------------------------------------------
// Pair kernel (DOMINANT): per-thread d-chunk streaming with __ldcs
// ---------------------------------------------------------------------------
__global__ void __launch_bounds__(256, 7) pair_kernel(
    const float* __restrict__ rel_pos,
    const float* __restrict__ wr0, const float* __restrict__ wr1, const float* __restrict__ wr2,
    int buf)
{
    __shared__ __align__(16) float Hsm[288];
    __shared__ __align__(16) float Ysm[20];
    __shared__ __align__(16) float Gsm[1632];
    __shared__ __align__(16) float Wsum[3840];

    const int bid = blockIdx.x;
    const int i = bid >> 5, j = bid & 31;
    const int tid = threadIdx.x;

    for (int o = tid; o < 288; o += 256){
        int b = (o >= 144); int rm = o - b*144;
        int ms = rm >> 4, c = rm & 15;
        float v;
        if (ms == 0)     v = g_H0[(b*NA + i)*NC + c];
        else if (ms < 4) v = g_H1[((b*NA + i)*3 + (ms-1))*NC + c];
        else             v = g_H2[((b*NA + i)*5 + (ms-4))*NC + c];
        Hsm[o] = v;
    }
    if (tid < 2){
        int b = tid;
        const float* rp = rel_pos + ((size_t)((b*NA + i)*NA + j))*3;
        float px = rp[0], py = rp[1], pz = rp[2];
        float rr = sqrtf(px*px + py*py + pz*pz + 1e-6f);
        float x = px/rr, y = py/rr, z = pz/rr;
        Ysm[b*9+0] = 0.28209479f;
        Ysm[b*9+1] = 0.48860251f*y;
        Ysm[b*9+2] = 0.48860251f*z;
        Ysm[b*9+3] = 0.48860251f*x;
        Ysm[b*9+4] = 1.09254843f*x*y;
        Ysm[b*9+5] = 1.09254843f*y*z;
        Ysm[b*9+6] = 0.31539157f*(3.f*z*z - 1.f);
        Ysm[b*9+7] = 1.09254843f*x*z;
        Ysm[b*9+8] = 0.54627422f*(x*x - y*y);
    }
    __syncthreads();

    // Streaming phase: thread = (group g, c, co-quad); 16 independent
    // stride-64B float4 __ldcs loads per entry, no shuffles, no barriers.
    {
        const int g = tid >> 6, sub = tid & 63;
        const int c = sub >> 2, coq = sub & 3;
        const size_t pr = (size_t)(i*NA + j);
        const int lofs = c*256 + coq*4;
        #pragma unroll
        for (int k = 0; k < 4; k++){
            const int e = g + k*4;
            if (e < 15){
                const float* bp;
                if (e < 3)      bp = wr0 + pr*12288 + (size_t)e*4096;
                else if (e < 9) bp = wr1 + pr*24576 + (size_t)(e-3)*4096;
                else            bp = wr2 + pr*24576 + (size_t)(e-9)*4096;
                bp += lofs;
                float4 a0 = make_float4(0.f,0.f,0.f,0.f);
                float4 a1 = make_float4(0.f,0.f,0.f,0.f);
                #pragma unroll
                for (int d = 0; d < 16; d += 2){
                    float4 w0 = __ldcs((const float4*)(bp + d*16));
                    float4 w1 = __ldcs((const float4*)(bp + (d+1)*16));
                    a0.x += w0.x; a0.y += w0.y; a0.z += w0.z; a0.w += w0.w;
                    a1.x += w1.x; a1.y += w1.y; a1.z += w1.z; a1.w += w1.w;
                }
                a0.x += a1.x; a0.y += a1.y; a0.z += a1.z; a0.w += a1.w;
                *(float4*)&Wsum[e*256 + c*16 + coq*4] = a0;
            }
        }
    }

    // G phase (tiny ALU, overlaps the in-flight stream loads)
    {
        int wid = tid >> 5, gb = (tid >> 4) & 1, gc = tid & 15;
        g_all<0>(wid, gb, gc, Hsm, Ysm, Gsm);
    }
    __syncthreads();

    // Final small matvec + atomic accumulation over j
    float* P0 = g_P0[buf];
    float* P1 = g_P1[buf];
    float* P2 = g_P2[buf];
    for (int o = tid; o < 288; o += 256){
        int co = o & 15;
        int t = o >> 4;
        int b = (t >= 9);
        int ms = t - b*9;
        float s = 0.f;
        if (ms == 0){
            #pragma unroll
            for (int e = 0; e < 3; e++)
                #pragma unroll
                for (int c = 0; c < 16; c++)
                    s += Gsm[b*816 + e*16 + c] * Wsum[e*256 + c*16 + co];
            atomicAdd(&P0[(b*NA + i)*NC + co], s);
        } else if (ms < 4){
            int z = ms - 1;
            #pragma unroll
            for (int ee = 0; ee < 6; ee++)
                #pragma unroll
                for (int c = 0; c < 16; c++)
                    s += Gsm[b*816 + 48 + ee*48 + z*16 + c] * Wsum[(3+ee)*256 + c*16 + co];
            atomicAdd(&P1[((b*NA + i)*3 + z)*NC + co], s);
        } else {
            int z = ms - 4;
            #pragma unroll
            for (int ee = 0; ee < 6; ee++)
                #pragma unroll
                for (int c = 0; c < 16; c++)
                    s += Gsm[b*816 + 336 + ee*80 + z*16 + c] * Wsum[(9+ee)*256 + c*16 + co];
            atomicAdd(&P2[((b*NA + i)*5 + z)*NC + co], s);
        }
    }
}

// ---------------------------------------------------------------------------
// Scalars kernel (layer 1 only; layer 0 fused into the second site launch)
// ---------------------------------------------------------------------------
__global__ void __launch_bounds__(256) scalars_kernel(float* __restrict__ out, int layer){
    int bid = blockIdx.x;
    int b = bid >> 5, a = bid & 31;
    int tid = threadIdx.x;
    __shared__ __align__(16) float Psm[144];
    if (tid < 144){
        int ms = tid >> 4, c = tid & 15;
        float v;
        if (ms == 0)       v = g_P0[layer][(b*NA + a)*NC + c];
        else if (ms < 4)   v = g_P1[layer][((b*NA + a)*3 + (ms-1))*NC + c];
        else               v = g_P2[layer][((b*NA + a)*5 + (ms-4))*NC + c];
        Psm[tid] = v;
    }
    __syncthreads();
    float* o = out + (size_t)((layer*NB + b)*NA + a)*784;
    if (tid < 16) o[tid] = Psm[tid];
    int cc = tid >> 4, dd = tid & 15;
    o[16  + tid] = Psm[cc]*Psm[dd];
    float s1 = 0.f;
    #pragma unroll
    for (int m = 0; m < 3; m++) s1 += Psm[(1+m)*16 + cc]*Psm[(1+m)*16 + dd];
    o[272 + tid] = s1;
    float s2 = 0.f;
    #pragma unroll
    for (int m = 0; m < 5; m++) s2 += Psm[(4+m)*16 + cc]*Psm[(4+m)*16 + dd];
    o[528 + tid] = s2;
}

// ---------------------------------------------------------------------------
// Launch: 6 kernels
// ---------------------------------------------------------------------------
extern "C" void kernel_launch(void* const* d_in, const int* in_sizes, int n_in,
                              void* d_out, int out_size)
{
    const float* v0    = (const float*)d_in[0];
    const float* v1    = (const float*)d_in[1];
    const float* v2    = (const float*)d_in[2];
    const float* rel   = (const float*)d_in[3];
    const float* norms = (const float*)d_in[4];
    const float* wnl[2][3]  = {{(const float*)d_in[5],  (const float*)d_in[7],  (const float*)d_in[9]},
                               {(const float*)d_in[11], (const float*)d_in[13], (const float*)d_in[15]}};
    const float* wrel[2][3] = {{(const float*)d_in[6],  (const float*)d_in[8],  (const float*)d_in[10]},
                               {(const float*)d_in[12], (const float*)d_in[14], (const float*)d_in[16]}};
    float* out = (float*)d_out;

    zero_parts_kernel<<<72, 256>>>();
    site_kernel<<<dim3(64,3), 256>>>(1, v0, v1, v2, norms,
                                     wnl[0][0], wnl[0][1], wnl[0][2], 0, out);
    pair_kernel<<<1024, 256>>>(rel, wrel[0][0], wrel[0][1], wrel[0][2], 0);
    site_kernel<<<dim3(64,3), 256>>>(0, v0, v1, v2, norms,
                                     wnl[1][0], wnl[1][1], wnl[1][2], 1, out);
    pair_kernel<<<1024, 256>>>(rel, wrel[1][0], wrel[1][1], wrel[1][2], 1);
    scalars_kernel<<<64, 256>>>(out, 1);
}

// round 14
// speedup vs baseline: 3.5080x; 1.0438x over previous
#include <cuda_runtime.h>
#include <math.h>

#define NA 32
#define NB 2
#define NC 16

// ---------------------------------------------------------------------------
// Compile-time tables
// ---------------------------------------------------------------------------
constexpr int E_L_[15]   = {0,0,0, 1,1,1,1,1,1, 2,2,2,2,2,2};
constexpr int E_L1_[15]  = {0,1,2, 0,1,1,1,2,2, 0,1,1,2,2,2};
constexpr int E_L2_[15]  = {0,1,2, 1,0,1,2,1,2, 2,1,2,0,1,2};
constexpr int E_CG_[15]  = {0,44,390, 1,35,53,125,270,415, 10,80,170,245,315,490};
constexpr int E_TAU_[15] = {0,256,512, 0,256,512,768,1024,1280, 0,256,512,768,1024,1280};
constexpr int E_GOFF_[15]= {0,16,32, 48,96,144,192,240,288, 336,416,496,576,656,736};
constexpr int MB_[3] = {0,1,4};
__host__ __device__ constexpr int SB_(int e){ return e<3 ? e : (e<9 ? 3+(e-3)*3 : 21+(e-9)*5); }

constexpr double cfact(int n){ double r=1.0; for (int k=2;k<=n;k++) r*= (double)k; return r; }
constexpr double csqrt_(double x){ double g = x > 1.0 ? x : 1.0; for (int i=0;i<80;i++) g = 0.5*(g + x/g); return g; }
constexpr double cg_coeff(int l1,int l2,int l,int m1,int m2,int m){
    int lo = l1>l2 ? l1-l2 : l2-l1;
    if (m1+m2 != m || l < lo || l > l1+l2) return 0.0;
    double pre = csqrt_((2.0*l+1.0)*cfact(l+l1-l2)*cfact(l-l1+l2)*cfact(l1+l2-l)/cfact(l1+l2+l+1));
    pre *= csqrt_(cfact(l+m)*cfact(l-m)*cfact(l1+m1)*cfact(l1-m1)*cfact(l2+m2)*cfact(l2-m2));
    double s = 0.0;
    for (int k=0;k<=l1+l2;k++){
        int d0=k,d1=l1+l2-l-k,d2=l1-m1-k,d3=l2+m2-k,d4=l-l2+m1+k,d5=l-l1-m2+k;
        if (d0<0||d1<0||d2<0||d3<0||d4<0||d5<0) continue;
        double t = 1.0/(cfact(d0)*cfact(d1)*cfact(d2)*cfact(d3)*cfact(d4)*cfact(d5));
        s += (k&1) ? -t : t;
    }
    return pre*s;
}
struct CGTable {
    float v[615];
    constexpr CGTable() : v{} {
        int off = 0;
        for (int l1=0;l1<=2;l1++)
            for (int l2=0;l2<=2;l2++){
                int lmin = l1>l2 ? l1-l2 : l2-l1;
                int lmax = (l1+l2) < 2 ? (l1+l2) : 2;
                for (int l=lmin;l<=lmax;l++){
                    int n1=2*l1+1, n2=2*l2+1, nl=2*l+1;
                    for (int x=0;x<n1;x++)
                        for (int y=0;y<n2;y++)
                            for (int z=0;z<nl;z++)
                                v[off + (x*n2+y)*nl + z] = (float)cg_coeff(l1,l2,l, x-l1, y-l2, z-l);
                    off += n1*n2*nl;
                }
            }
    }
};
__constant__ CGTable CGT{};

// ---------------------------------------------------------------------------
// Scratch — H and P double-buffered; all zeroed once upfront
// ---------------------------------------------------------------------------
__device__ float g_H0[2][NB*NA*1*NC];
__device__ float g_H1[2][NB*NA*3*NC];
__device__ float g_H2[2][NB*NA*5*NC];
__device__ float g_P0[2][NB*NA*1*NC];
__device__ float g_P1[2][NB*NA*3*NC];
__device__ float g_P2[2][NB*NA*5*NC];

__global__ void __launch_bounds__(256) zero_parts_kernel(){
    int t = blockIdx.x * blockDim.x + threadIdx.x;
    if (t < 2*NB*NA*1*NC){ ((float*)g_P0)[t] = 0.f; ((float*)g_H0)[t] = 0.f; }
    if (t < 2*NB*NA*3*NC){ ((float*)g_P1)[t] = 0.f; ((float*)g_H1)[t] = 0.f; }
    if (t < 2*NB*NA*5*NC){ ((float*)g_P2)[t] = 0.f; ((float*)g_H2)[t] = 0.f; }
}

// ---------------------------------------------------------------------------
// Site kernel v3: grid (64 sites, 15 entries). One entry per block:
// tiny mp + T, 16 KB weight stream @ MLP16, atomicAdd into H[buf].
// ---------------------------------------------------------------------------
template<int E>
__device__ __forceinline__ void site_T1(int tid, int r, int co,
    const float* __restrict__ mpsm, float* __restrict__ Tsm)
{
    constexpr int l  = E_L_[E], l1 = E_L1_[E], l2 = E_L2_[E];
    constexpr int nz = 2*l+1, n1 = 2*l1+1, n2 = 2*l2+1;
    constexpr int cgo = E_CG_[E], mb1 = MB_[l1], mb2 = MB_[l2];
    #pragma unroll
    for (int z = 0; z < nz; z++){
        float tv = 0.f;
        #pragma unroll
        for (int x = 0; x < n1; x++){
            float hx = mpsm[(mb1+x)*16 + r];
            #pragma unroll
            for (int y = 0; y < n2; y++)
                tv += CGT.v[cgo + (x*n2+y)*nz + z] * hx * mpsm[(mb2+y)*16 + co];
        }
        Tsm[z*256 + tid] = tv;
    }
}

template<int E>
__device__ __forceinline__ void site_entry_run(int b, int i, int tid, int r, int co,
    const float* __restrict__ mpsm, float* __restrict__ Tsm, float* __restrict__ red,
    const float* __restrict__ wnl0, const float* __restrict__ wnl1, const float* __restrict__ wnl2,
    int buf)
{
    constexpr int l = E_L_[E];
    constexpr int nz = 2*l+1;
    constexpr int TAUO = E_TAU_[E]*16;   // force compile-time fold (host constexpr array)

    const float* wb;
    if constexpr (E < 3)      wb = wnl0 + (size_t)i*768*16  + TAUO;
    else if constexpr (E < 9) wb = wnl1 + (size_t)i*1536*16 + TAUO;
    else                      wb = wnl2 + (size_t)i*1536*16 + TAUO;

    site_T1<E>(tid, r, co, mpsm, Tsm);
    __syncthreads();

    float acc[nz];
    #pragma unroll
    for (int z = 0; z < nz; z++) acc[z] = 0.f;
    #pragma unroll
    for (int it = 0; it < 16; it++){
        float w = __ldcs(wb + (it*16 + r)*16 + co);
        #pragma unroll
        for (int z = 0; z < nz; z++)
            acc[z] += Tsm[z*256 + it*16 + r] * w;
    }

    #pragma unroll
    for (int z = 0; z < nz; z++)
        red[(r*nz + z)*16 + co] = acc[z];
    __syncthreads();
    if (tid < nz*16){
        int z = tid >> 4, c = tid & 15;
        float s = 0.f;
        #pragma unroll
        for (int rr = 0; rr < 16; rr++) s += red[(rr*nz + z)*16 + c];
        if constexpr (l == 0)      atomicAdd(&g_H0[buf][(b*NA + i)*NC + c], s);
        else if constexpr (l == 1) atomicAdd(&g_H1[buf][((b*NA + i)*3 + z)*NC + c], s);
        else                       atomicAdd(&g_H2[buf][((b*NA + i)*5 + z)*NC + c], s);
    }
}

__global__ void __launch_bounds__(256) site_kernel(
    int use_inputs,
    const float* __restrict__ v0, const float* __restrict__ v1, const float* __restrict__ v2,
    const float* __restrict__ norms,
    const float* __restrict__ wnl0, const float* __restrict__ wnl1, const float* __restrict__ wnl2,
    int buf, int doScal, float* __restrict__ out)
{
    int bi = blockIdx.x;          // 0..63  (b*32+i)
    int e  = blockIdx.y;          // 0..14  coupling entry
    int b = bi >> 5, i = bi & 31;
    int tid = threadIdx.x;

    __shared__ __align__(16) float msm[32];
    __shared__ __align__(16) float mpsm[9*16];
    __shared__ __align__(16) float Tsm[5*256];
    __shared__ __align__(16) float red[16*5*16];
    __shared__ __align__(16) float Psm[144];

    const float* P0 = use_inputs ? v0 : g_P0[0];
    const float* P1 = use_inputs ? v1 : g_P1[0];
    const float* P2 = use_inputs ? v2 : g_P2[0];

    if (tid < 32)
        msm[tid] = (norms[(b*NA + i)*NA + tid] < 0.5f) ? 1.f : 0.f;
    __syncthreads();

    if (tid < 144){
        int ms = tid >> 4, c = tid & 15;
        int l, m;
        if (ms == 0){ l = 0; m = 0; } else if (ms < 4){ l = 1; m = ms-1; } else { l = 2; m = ms-4; }
        const float* P = (l==0) ? P0 : ((l==1) ? P1 : P2);
        int nm = 2*l+1;
        float s = 0.f;
        #pragma unroll 8
        for (int j = 0; j < 32; j++)
            s += msm[j] * P[((b*NA + j)*nm + m)*NC + c];
        mpsm[tid] = s;
    }
    __syncthreads();

    int r = tid >> 4, co = tid & 15;
    switch (e){
        case 0:  site_entry_run<0 >(b,i,tid,r,co,mpsm,Tsm,red,wnl0,wnl1,wnl2,buf); break;
        case 1:  site_entry_run<1 >(b,i,tid,r,co,mpsm,Tsm,red,wnl0,wnl1,wnl2,buf); break;
        case 2:  site_entry_run<2 >(b,i,tid,r,co,mpsm,Tsm,red,wnl0,wnl1,wnl2,buf); break;
        case 3:  site_entry_run<3 >(b,i,tid,r,co,mpsm,Tsm,red,wnl0,wnl1,wnl2,buf); break;
        case 4:  site_entry_run<4 >(b,i,tid,r,co,mpsm,Tsm,red,wnl0,wnl1,wnl2,buf); break;
        case 5:  site_entry_run<5 >(b,i,tid,r,co,mpsm,Tsm,red,wnl0,wnl1,wnl2,buf); break;
        case 6:  site_entry_run<6 >(b,i,tid,r,co,mpsm,Tsm,red,wnl0,wnl1,wnl2,buf); break;
        case 7:  site_entry_run<7 >(b,i,tid,r,co,mpsm,Tsm,red,wnl0,wnl1,wnl2,buf); break;
        case 8:  site_entry_run<8 >(b,i,tid,r,co,mpsm,Tsm,red,wnl0,wnl1,wnl2,buf); break;
        case 9:  site_entry_run<9 >(b,i,tid,r,co,mpsm,Tsm,red,wnl0,wnl1,wnl2,buf); break;
        case 10: site_entry_run<10>(b,i,tid,r,co,mpsm,Tsm,red,wnl0,wnl1,wnl2,buf); break;
        case 11: site_entry_run<11>(b,i,tid,r,co,mpsm,Tsm,red,wnl0,wnl1,wnl2,buf); break;
        case 12: site_entry_run<12>(b,i,tid,r,co,mpsm,Tsm,red,wnl0,wnl1,wnl2,buf); break;
        case 13: site_entry_run<13>(b,i,tid,r,co,mpsm,Tsm,red,wnl0,wnl1,wnl2,buf); break;
        default: site_entry_run<14>(b,i,tid,r,co,mpsm,Tsm,red,wnl0,wnl1,wnl2,buf); break;
    }

    // Fused scalars for the PREVIOUS layer (P[0] final before this launch runs)
    if (doScal && e == 0){
        __syncthreads();
        if (tid < 144){
            int ms = tid >> 4, c = tid & 15;
            float v;
            if (ms == 0)       v = g_P0[0][(b*NA + i)*NC + c];
            else if (ms < 4)   v = g_P1[0][((b*NA + i)*3 + (ms-1))*NC + c];
            else               v = g_P2[0][((b*NA + i)*5 + (ms-4))*NC + c];
            Psm[tid] = v;
        }
        __syncthreads();
        float* o = out + (size_t)((0*NB + b)*NA + i)*784;
        if (tid < 16) o[tid] = Psm[tid];
        int cc = tid >> 4, dd = tid & 15;
        o[16  + tid] = Psm[cc]*Psm[dd];
        float s1 = 0.f;
        #pragma unroll
        for (int m = 0; m < 3; m++) s1 += Psm[(1+m)*16 + cc]*Psm[(1+m)*16 + dd];
        o[272 + tid] = s1;
        float s2 = 0.f;
        #pragma unroll
        for (int m = 0; m < 5; m++) s2 += Psm[(4+m)*16 + cc]*Psm[(4+m)*16 + dd];
        o[528 + tid] = s2;
    }
}

// ---------------------------------------------------------------------------
// Pair kernel: G helpers
// ---------------------------------------------------------------------------
template<int E>
__device__ __forceinline__ void g_entry(int wid, int gb, int gc,
    const float* __restrict__ Hsm, const float* __restrict__ Ysm, float* __restrict__ Gsm)
{
    constexpr int l  = E_L_[E], l1 = E_L1_[E], l2 = E_L2_[E];
    constexpr int nz = 2*l+1, n1 = 2*l1+1, n2 = 2*l2+1;
    constexpr int cgo = E_CG_[E], mb1 = MB_[l1], mb2 = MB_[l2], goff = E_GOFF_[E];
    #pragma unroll
    for (int z = 0; z < nz; z++){
        if (((SB_(E) + z) & 7) == wid){
            float s = 0.f;
            #pragma unroll
            for (int x = 0; x < n1; x++){
                float hx = Hsm[gb*144 + (mb1+x)*16 + gc];
                #pragma unroll
                for (int y = 0; y < n2; y++)
                    s += CGT.v[cgo + (x*n2+y)*nz + z] * Ysm[gb*9 + mb2 + y] * hx;
            }
            Gsm[gb*816 + goff + z*16 + gc] = s;
        }
    }
}

template<int E>
__device__ __forceinline__ void g_all(int wid, int gb, int gc,
    const float* __restrict__ Hsm, const float* __restrict__ Ysm, float* __restrict__ Gsm)
{
    g_entry<E>(wid, gb, gc, Hsm, Ysm, Gsm);
    if constexpr (E+1 < 15) g_all<E+1>(wid, gb, gc, Hsm, Ysm, Gsm);
}

// ---------------------------------------------------------------------------
// Pair kernel (DOMINANT): per-thread d-chunk streaming with __ldcs
// ---------------------------------------------------------------------------
__global__ void __launch_bounds__(256, 7) pair_kernel(
    const float* __restrict__ rel_pos,
    const float* __restrict__ wr0, const float* __restrict__ wr1, const float* __restrict__ wr2,
    int buf)
{
    __shared__ __align__(16) float Hsm[288];
    __shared__ __align__(16) float Ysm[20];
    __shared__ __align__(16) float Gsm[1632];
    __shared__ __align__(16) float Wsum[3840];

    const int bid = blockIdx.x;
    const int i = bid >> 5, j = bid & 31;
    const int tid = threadIdx.x;

    for (int o = tid; o < 288; o += 256){
        int b = (o >= 144); int rm = o - b*144;
        int ms = rm >> 4, c = rm & 15;
        float v;
        if (ms == 0)     v = g_H0[buf][(b*NA + i)*NC + c];
        else if (ms < 4) v = g_H1[buf][((b*NA + i)*3 + (ms-1))*NC + c];
        else             v = g_H2[buf][((b*NA + i)*5 + (ms-4))*NC + c];
        Hsm[o] = v;
    }
    if (tid < 2){
        int b = tid;
        const float* rp = rel_pos + ((size_t)((b*NA + i)*NA + j))*3;
        float px = rp[0], py = rp[1], pz = rp[2];
        float rr = sqrtf(px*px + py*py + pz*pz + 1e-6f);
        float x = px/rr, y = py/rr, z = pz/rr;
        Ysm[b*9+0] = 0.28209479f;
        Ysm[b*9+1] = 0.48860251f*y;
        Ysm[b*9+2] = 0.48860251f*z;
        Ysm[b*9+3] = 0.48860251f*x;
        Ysm[b*9+4] = 1.09254843f*x*y;
        Ysm[b*9+5] = 1.09254843f*y*z;
        Ysm[b*9+6] = 0.31539157f*(3.f*z*z - 1.f);
        Ysm[b*9+7] = 1.09254843f*x*z;
        Ysm[b*9+8] = 0.54627422f*(x*x - y*y);
    }
    __syncthreads();

    // Streaming phase: thread = (group g, c, co-quad); 16 independent
    // stride-64B float4 __ldcs loads per entry, no shuffles, no barriers.
    {
        const int g = tid >> 6, sub = tid & 63;
        const int c = sub >> 2, coq = sub & 3;
        const size_t pr = (size_t)(i*NA + j);
        const int lofs = c*256 + coq*4;
        #pragma unroll
        for (int k = 0; k < 4; k++){
            const int e = g + k*4;
            if (e < 15){
                const float* bp;
                if (e < 3)      bp = wr0 + pr*12288 + (size_t)e*4096;
                else if (e < 9) bp = wr1 + pr*24576 + (size_t)(e-3)*4096;
                else            bp = wr2 + pr*24576 + (size_t)(e-9)*4096;
                bp += lofs;
                float4 a0 = make_float4(0.f,0.f,0.f,0.f);
                float4 a1 = make_float4(0.f,0.f,0.f,0.f);
                #pragma unroll
                for (int d = 0; d < 16; d += 2){
                    float4 w0 = __ldcs((const float4*)(bp + d*16));
                    float4 w1 = __ldcs((const float4*)(bp + (d+1)*16));
                    a0.x += w0.x; a0.y += w0.y; a0.z += w0.z; a0.w += w0.w;
                    a1.x += w1.x; a1.y += w1.y; a1.z += w1.z; a1.w += w1.w;
                }
                a0.x += a1.x; a0.y += a1.y; a0.z += a1.z; a0.w += a1.w;
                *(float4*)&Wsum[e*256 + c*16 + coq*4] = a0;
            }
        }
    }

    // G phase (tiny ALU, overlaps the in-flight stream loads)
    {
        int wid = tid >> 5, gb = (tid >> 4) & 1, gc = tid & 15;
        g_all<0>(wid, gb, gc, Hsm, Ysm, Gsm);
    }
    __syncthreads();

    // Final small matvec + atomic accumulation over j
    float* P0 = g_P0[buf];
    float* P1 = g_P1[buf];
    float* P2 = g_P2[buf];
    for (int o = tid; o < 288; o += 256){
        int co = o & 15;
        int t = o >> 4;
        int b = (t >= 9);
        int ms = t - b*9;
        float s = 0.f;
        if (ms == 0){
            #pragma unroll
            for (int e = 0; e < 3; e++)
                #pragma unroll
                for (int c = 0; c < 16; c++)
                    s += Gsm[b*816 + e*16 + c] * Wsum[e*256 + c*16 + co];
            atomicAdd(&P0[(b*NA + i)*NC + co], s);
        } else if (ms < 4){
            int z = ms - 1;
            #pragma unroll
            for (int ee = 0; ee < 6; ee++)
                #pragma unroll
                for (int c = 0; c < 16; c++)
                    s += Gsm[b*816 + 48 + ee*48 + z*16 + c] * Wsum[(3+ee)*256 + c*16 + co];
            atomicAdd(&P1[((b*NA + i)*3 + z)*NC + co], s);
        } else {
            int z = ms - 4;
            #pragma unroll
            for (int ee = 0; ee < 6; ee++)
                #pragma unroll
                for (int c = 0; c < 16; c++)
                    s += Gsm[b*816 + 336 + ee*80 + z*16 + c] * Wsum[(9+ee)*256 + c*16 + co];
            atomicAdd(&P2[((b*NA + i)*5 + z)*NC + co], s);
        }
    }
}

// ---------------------------------------------------------------------------
// Scalars kernel (layer 1 only; layer 0 fused into the second site launch)
// ---------------------------------------------------------------------------
__global__ void __launch_bounds__(256) scalars_kernel(float* __restrict__ out, int layer){
    int bid = blockIdx.x;
    int b = bid >> 5, a = bid & 31;
    int tid = threadIdx.x;
    __shared__ __align__(16) float Psm[144];
    if (tid < 144){
        int ms = tid >> 4, c = tid & 15;
        float v;
        if (ms == 0)       v = g_P0[layer][(b*NA + a)*NC + c];
        else if (ms < 4)   v = g_P1[layer][((b*NA + a)*3 + (ms-1))*NC + c];
        else               v = g_P2[layer][((b*NA + a)*5 + (ms-4))*NC + c];
        Psm[tid] = v;
    }
    __syncthreads();
    float* o = out + (size_t)((layer*NB + b)*NA + a)*784;
    if (tid < 16) o[tid] = Psm[tid];
    int cc = tid >> 4, dd = tid & 15;
    o[16  + tid] = Psm[cc]*Psm[dd];
    float s1 = 0.f;
    #pragma unroll
    for (int m = 0; m < 3; m++) s1 += Psm[(1+m)*16 + cc]*Psm[(1+m)*16 + dd];
    o[272 + tid] = s1;
    float s2 = 0.f;
    #pragma unroll
    for (int m = 0; m < 5; m++) s2 += Psm[(4+m)*16 + cc]*Psm[(4+m)*16 + dd];
    o[528 + tid] = s2;
}

// ---------------------------------------------------------------------------
// Launch: 6 kernels
// ---------------------------------------------------------------------------
extern "C" void kernel_launch(void* const* d_in, const int* in_sizes, int n_in,
                              void* d_out, int out_size)
{
    const float* v0    = (const float*)d_in[0];
    const float* v1    = (const float*)d_in[1];
    const float* v2    = (const float*)d_in[2];
    const float* rel   = (const float*)d_in[3];
    const float* norms = (const float*)d_in[4];
    const float* wnl[2][3]  = {{(const float*)d_in[5],  (const float*)d_in[7],  (const float*)d_in[9]},
                               {(const float*)d_in[11], (const float*)d_in[13], (const float*)d_in[15]}};
    const float* wrel[2][3] = {{(const float*)d_in[6],  (const float*)d_in[8],  (const float*)d_in[10]},
                               {(const float*)d_in[12], (const float*)d_in[14], (const float*)d_in[16]}};
    float* out = (float*)d_out;

    zero_parts_kernel<<<72, 256>>>();
    site_kernel<<<dim3(64,15), 256>>>(1, v0, v1, v2, norms,
                                      wnl[0][0], wnl[0][1], wnl[0][2], 0, 0, out);
    pair_kernel<<<1024, 256>>>(rel, wrel[0][0], wrel[0][1], wrel[0][2], 0);
    site_kernel<<<dim3(64,15), 256>>>(0, v0, v1, v2, norms,
                                      wnl[1][0], wnl[1][1], wnl[1][2], 1, 1, out);
    pair_kernel<<<1024, 256>>>(rel, wrel[1][0], wrel[1][1], wrel[1][2], 1);
    scalars_kernel<<<64, 256>>>(out, 1);
}